// round 10
// baseline (speedup 1.0000x reference)
#include <cuda_runtime.h>
#include <cstdint>

// x [4,256,256,128], DIM=HID=128, R = 262144 rows.
constexpr int LDA = 132;   // k_pre activation tile ld: conflict-free
constexpr int LDP = 133;   // k_post activation tile ld
constexpr int WLD = 136;   // weight / k-major tiles: banks 8*tg+g, conflict-free

constexpr int SMEM_PRE  = (128 * LDA + 2 * 128 * WLD) * 4;  // 206,848
constexpr int SMEM_MIX  = (4 * 32 * WLD) * 4;               // 69,632 (2-stage)
constexpr int SMEM_POST = (64 * LDP + 128 * WLD) * 4;       // 103,680

// Scratch (device globals). 4 x 134 MB.
__device__ float g_leftT [33554432];  // [b][d][k][j]  (tf32-rounded)
__device__ float g_rightT[33554432];  // [b][d][k][i]  (tf32-rounded)
__device__ float g_ogate [33554432];  // [r][d]
__device__ float g_mixT  [33554432];  // [b][d][i][j]

__device__ __forceinline__ float to_tf32(float x) {
    float r;
    asm("cvt.rna.tf32.f32 %0, %1;" : "=f"(r) : "f"(x));
    return r;
}
__device__ __forceinline__ float sigm(float x) { return 1.0f / (1.0f + __expf(-x)); }

__device__ __forceinline__ void mma8(float c[4], const uint32_t a[4], uint32_t b0, uint32_t b1) {
    asm volatile(
        "mma.sync.aligned.m16n8k8.row.col.f32.tf32.tf32.f32 "
        "{%0,%1,%2,%3},{%4,%5,%6,%7},{%8,%9},{%0,%1,%2,%3};\n"
        : "+f"(c[0]), "+f"(c[1]), "+f"(c[2]), "+f"(c[3])
        : "r"(a[0]), "r"(a[1]), "r"(a[2]), "r"(a[3]), "r"(b0), "r"(b1));
}

template <int NT>
__device__ __forceinline__ void zacc2(float (&a)[2][NT][4]) {
#pragma unroll
    for (int i = 0; i < 2; i++)
#pragma unroll
        for (int j = 0; j < NT; j++)
#pragma unroll
            for (int k = 0; k < 4; k++) a[i][j][k] = 0.f;
}

// ---- k_pre dual GEMM: A(row-major ld=LDA) shared, two B's. Warp tile 32 x NT*8 ----
template <int NT>
__device__ __forceinline__ void gemm_dual(const float* __restrict__ sa,
                                          const float* __restrict__ wA,
                                          const float* __restrict__ wB,
                                          float (&acc1)[2][NT][4], float (&acc2)[2][NT][4],
                                          int m_base, int n_base, int g, int tg) {
#pragma unroll
    for (int kk = 0; kk < 128; kk += 8) {
        uint32_t a[2][4];
#pragma unroll
        for (int mt = 0; mt < 2; ++mt) {
            int r = m_base + mt * 16;
            a[mt][0] = __float_as_uint(sa[(r + g) * LDA + kk + tg]);
            a[mt][1] = __float_as_uint(sa[(r + 8 + g) * LDA + kk + tg]);
            a[mt][2] = __float_as_uint(sa[(r + g) * LDA + kk + 4 + tg]);
            a[mt][3] = __float_as_uint(sa[(r + 8 + g) * LDA + kk + 4 + tg]);
        }
#pragma unroll
        for (int nt = 0; nt < NT; ++nt) {
            int cn = n_base + nt * 8 + g;
            uint32_t b00 = __float_as_uint(wA[(kk + tg) * WLD + cn]);
            uint32_t b01 = __float_as_uint(wA[(kk + 4 + tg) * WLD + cn]);
            uint32_t b10 = __float_as_uint(wB[(kk + tg) * WLD + cn]);
            uint32_t b11 = __float_as_uint(wB[(kk + 4 + tg) * WLD + cn]);
            mma8(acc1[0][nt], a[0], b00, b01);
            mma8(acc1[1][nt], a[1], b00, b01);
            mma8(acc2[0][nt], a[0], b10, b11);
            mma8(acc2[1][nt], a[1], b10, b11);
        }
    }
}

// ogate GEMM: A from smem, B straight from GLOBAL with tf32 rounding (no smem staging).
// Identical numerics to the smem path (same RNA cvt before HMMA).
template <int NT>
__device__ __forceinline__ void gemm_gB(const float* __restrict__ sa,
                                        const float* __restrict__ W,
                                        float (&acc)[2][NT][4],
                                        int m_base, int n_base, int g, int tg) {
#pragma unroll
    for (int kk = 0; kk < 128; kk += 8) {
        uint32_t a[2][4];
#pragma unroll
        for (int mt = 0; mt < 2; ++mt) {
            int r = m_base + mt * 16;
            a[mt][0] = __float_as_uint(sa[(r + g) * LDA + kk + tg]);
            a[mt][1] = __float_as_uint(sa[(r + 8 + g) * LDA + kk + tg]);
            a[mt][2] = __float_as_uint(sa[(r + g) * LDA + kk + 4 + tg]);
            a[mt][3] = __float_as_uint(sa[(r + 8 + g) * LDA + kk + 4 + tg]);
        }
#pragma unroll
        for (int nt = 0; nt < NT; ++nt) {
            int cn = n_base + nt * 8 + g;
            uint32_t b0 = __float_as_uint(to_tf32(__ldg(W + (kk + tg) * 128 + cn)));
            uint32_t b1 = __float_as_uint(to_tf32(__ldg(W + (kk + 4 + tg) * 128 + cn)));
            mma8(acc[0][nt], a[0], b0, b1);
            mma8(acc[1][nt], a[1], b0, b1);
        }
    }
}

template <int NT, int LD>
__device__ __forceinline__ void gemm_rowA(const float* __restrict__ sa,
                                          const float* __restrict__ sw,
                                          float (&acc)[2][NT][4],
                                          int m_base, int n_base, int g, int tg) {
#pragma unroll
    for (int kk = 0; kk < 128; kk += 8) {
        uint32_t a[2][4];
#pragma unroll
        for (int mt = 0; mt < 2; ++mt) {
            int r = m_base + mt * 16;
            a[mt][0] = __float_as_uint(sa[(r + g) * LD + kk + tg]);
            a[mt][1] = __float_as_uint(sa[(r + 8 + g) * LD + kk + tg]);
            a[mt][2] = __float_as_uint(sa[(r + g) * LD + kk + 4 + tg]);
            a[mt][3] = __float_as_uint(sa[(r + 8 + g) * LD + kk + 4 + tg]);
        }
#pragma unroll
        for (int nt = 0; nt < NT; ++nt) {
            int cn = n_base + nt * 8 + g;
            uint32_t b0 = __float_as_uint(sw[(kk + tg) * WLD + cn]);
            uint32_t b1 = __float_as_uint(sw[(kk + 4 + tg) * WLD + cn]);
            mma8(acc[0][nt], a[0], b0, b1);
            mma8(acc[1][nt], a[1], b0, b1);
        }
    }
}

// C += A^T*B, k-major 32-row chunks (ld=WLD)  -- k_mix
__device__ __forceinline__ void gemm_kT32(const float* __restrict__ sa,
                                          const float* __restrict__ sb,
                                          float (&acc)[2][8][4],
                                          int m_base, int n_base, int g, int tg) {
#pragma unroll
    for (int kk = 0; kk < 32; kk += 8) {
        uint32_t a[2][4];
#pragma unroll
        for (int mt = 0; mt < 2; ++mt) {
            int r = m_base + mt * 16;
            a[mt][0] = __float_as_uint(sa[(kk + tg) * WLD + r + g]);
            a[mt][1] = __float_as_uint(sa[(kk + tg) * WLD + r + 8 + g]);
            a[mt][2] = __float_as_uint(sa[(kk + 4 + tg) * WLD + r + g]);
            a[mt][3] = __float_as_uint(sa[(kk + 4 + tg) * WLD + r + 8 + g]);
        }
#pragma unroll
        for (int nt = 0; nt < 8; ++nt) {
            int cn = n_base + nt * 8 + g;
            uint32_t b0 = __float_as_uint(sb[(kk + tg) * WLD + cn]);
            uint32_t b1 = __float_as_uint(sb[(kk + 4 + tg) * WLD + cn]);
            mma8(acc[0][nt], a[0], b0, b1);
            mma8(acc[1][nt], a[1], b0, b1);
        }
    }
}

// Vectorized weight load + tf32 round into smem [k][n] (ld=WLD)
template <int NTHR>
__device__ __forceinline__ void loadW4(float* __restrict__ sw, const float* __restrict__ W, int tid) {
    for (int i = tid; i < 4096; i += NTHR) {
        float4 v = __ldg(reinterpret_cast<const float4*>(W) + i);
        float* d = sw + (i >> 5) * WLD + ((i & 31) << 2);
        float4 o = {to_tf32(v.x), to_tf32(v.y), to_tf32(v.z), to_tf32(v.w)};
        *reinterpret_cast<float4*>(d) = o;
    }
}

// combine + DIRECT transposed writeout to dstT[d][krow][j0+j]; 32B-coalesced per tg-group
template <int NT>
__device__ __forceinline__ void combine_direct(float* __restrict__ dstT, int krow, int j0,
                                               const float (&acc1)[2][NT][4], const float (&acc2)[2][NT][4],
                                               const float* __restrict__ blin, const float* __restrict__ bgat,
                                               int m_base, int n_base, int g, int tg) {
    const size_t rowoff = (size_t)krow * 256 + j0;
#pragma unroll
    for (int mt = 0; mt < 2; ++mt) {
        int j = m_base + mt * 16 + g;
#pragma unroll
        for (int nt = 0; nt < NT; ++nt) {
            int d0 = n_base + nt * 8 + tg * 2;
            float bl0 = blin[d0], bl1 = blin[d0 + 1];
            float bg0 = bgat[d0], bg1 = bgat[d0 + 1];
            float v00 = to_tf32((acc1[mt][nt][0] + bl0) * sigm(acc2[mt][nt][0] + bg0));
            float v01 = to_tf32((acc1[mt][nt][1] + bl1) * sigm(acc2[mt][nt][1] + bg1));
            float v10 = to_tf32((acc1[mt][nt][2] + bl0) * sigm(acc2[mt][nt][2] + bg0));
            float v11 = to_tf32((acc1[mt][nt][3] + bl1) * sigm(acc2[mt][nt][3] + bg1));
            float* p0 = dstT + (((size_t)d0) << 16) + rowoff + j;
            float* p1 = dstT + (((size_t)(d0 + 1)) << 16) + rowoff + j;
            p0[0] = v00;  p1[0] = v01;
            p0[8] = v10;  p1[8] = v11;
        }
    }
}

// ----- Kernel 1: LN + 5 projections (1024 thr, 32 warps, tile 32x16, 3 barriers) -----
__global__ void __launch_bounds__(1024, 1) k_pre(
    const float* __restrict__ x, const float* __restrict__ ng, const float* __restrict__ nb,
    const float* __restrict__ wL, const float* __restrict__ bL,
    const float* __restrict__ wR, const float* __restrict__ bR,
    const float* __restrict__ wLG, const float* __restrict__ bLG,
    const float* __restrict__ wRG, const float* __restrict__ bRG,
    const float* __restrict__ wOG, const float* __restrict__ bOG) {
    extern __shared__ float smem[];
    float* sx = smem;                      // 128 x LDA
    float* w0 = smem + 128 * LDA;          // 128 x WLD
    float* w1 = w0 + 128 * WLD;            // 128 x WLD

    const int tid = threadIdx.x, lane = tid & 31, warp = tid >> 5;
    const int g = lane >> 2, tg = lane & 3;
    const int r0 = blockIdx.x << 7;
    const int b = r0 >> 16, krow = (r0 >> 8) & 255, j0 = r0 & 255;
    const int m_base = (warp >> 3) * 32, n_base = (warp & 7) * 16;
    const size_t plane = ((size_t)b * 128) << 16;

    // Phase A: weight prefetch pair 1 + LayerNorm into sx (tf32)
    loadW4<1024>(w0, wL, tid);
    loadW4<1024>(w1, wLG, tid);
    {
        float4 g4 = reinterpret_cast<const float4*>(ng)[lane];
        float4 b4 = reinterpret_cast<const float4*>(nb)[lane];
        for (int row = warp * 4; row < warp * 4 + 4; ++row) {
            float4 v = reinterpret_cast<const float4*>(x + ((size_t)(r0 + row)) * 128)[lane];
            float s = v.x + v.y + v.z + v.w;
            float q = fmaf(v.x, v.x, fmaf(v.y, v.y, fmaf(v.z, v.z, v.w * v.w)));
#pragma unroll
            for (int o = 16; o; o >>= 1) {
                s += __shfl_xor_sync(0xffffffffu, s, o);
                q += __shfl_xor_sync(0xffffffffu, q, o);
            }
            float mu = s * 0.0078125f;
            float rs = rsqrtf(fmaf(-mu, mu, q * 0.0078125f) + 1e-5f);
            float4 o4 = {to_tf32(fmaf((v.x - mu) * rs, g4.x, b4.x)),
                         to_tf32(fmaf((v.y - mu) * rs, g4.y, b4.y)),
                         to_tf32(fmaf((v.z - mu) * rs, g4.z, b4.z)),
                         to_tf32(fmaf((v.w - mu) * rs, g4.w, b4.w))};
            *reinterpret_cast<float4*>(sx + row * LDA + lane * 4) = o4;
        }
    }
    __syncthreads();

    float acc1[2][2][4], acc2[2][2][4];

    // Phase B: left pair GEMMs + per-warp direct writeout (hides straggler skew)
    zacc2(acc1); zacc2(acc2);
    gemm_dual<2>(sx, w0, w1, acc1, acc2, m_base, n_base, g, tg);
    combine_direct<2>(g_leftT + plane, krow, j0, acc1, acc2, bL, bLG, m_base, n_base, g, tg);
    __syncthreads();

    // Phase C: prefetch wR/wRG
    loadW4<1024>(w0, wR, tid);
    loadW4<1024>(w1, wRG, tid);
    __syncthreads();

    // Phase D: right pair GEMMs + writeout; then ogate GEMM with B from GLOBAL
    // (no more barriers — tail streams unsynchronized)
    zacc2(acc1); zacc2(acc2);
    gemm_dual<2>(sx, w0, w1, acc1, acc2, m_base, n_base, g, tg);
    combine_direct<2>(g_rightT + plane, krow, j0, acc1, acc2, bR, bRG, m_base, n_base, g, tg);

    zacc2(acc2);
    gemm_gB<2>(sx, wOG, acc2, m_base, n_base, g, tg);
#pragma unroll
    for (int mt = 0; mt < 2; ++mt) {
        int row = m_base + mt * 16 + g;
#pragma unroll
        for (int nt = 0; nt < 2; ++nt) {
            int cn = n_base + nt * 8 + tg * 2;
            float bg0 = bOG[cn], bg1 = bOG[cn + 1];
            float2 p0 = {sigm(acc2[mt][nt][0] + bg0), sigm(acc2[mt][nt][1] + bg1)};
            float2 p1 = {sigm(acc2[mt][nt][2] + bg0), sigm(acc2[mt][nt][3] + bg1)};
            *reinterpret_cast<float2*>(g_ogate + ((size_t)(r0 + row)) * 128 + cn) = p0;
            *reinterpret_cast<float2*>(g_ogate + ((size_t)(r0 + row + 8)) * 128 + cn) = p1;
        }
    }
}

// -------------------- Kernel 2: triangle einsum (2-stage cp.async, R8 config) ------------
__device__ __forceinline__ void cp_tile32(float* __restrict__ sdst, const float* __restrict__ gsrc, int tid) {
#pragma unroll
    for (int m = 0; m < 4; ++m) {
        int i = tid + m * 256;
        int row = i >> 5, seg = (i & 31) << 2;
        uint32_t dst = (uint32_t)__cvta_generic_to_shared(sdst + row * WLD + seg);
        asm volatile("cp.async.ca.shared.global [%0], [%1], 16;\n"
                     :: "r"(dst), "l"(gsrc + row * 256 + seg));
    }
}
#define CP_COMMIT asm volatile("cp.async.commit_group;\n")

__global__ void __launch_bounds__(256, 2) k_mix() {
    extern __shared__ float smemf[];
    float* sA[2] = {smemf, smemf + 32 * WLD};
    float* sB[2] = {smemf + 2 * 32 * WLD, smemf + 3 * 32 * WLD};

    const int tid = threadIdx.x, lane = tid & 31, warp = tid >> 5;
    const int g = lane >> 2, tg = lane & 3;
    const int b = blockIdx.z, d = blockIdx.y;
    const int i0 = (blockIdx.x >> 1) << 7, jj0 = (blockIdx.x & 1) << 7;
    const int m_base = (warp >> 1) * 32, n_base = (warp & 1) * 64;

    const size_t plane = ((size_t)(b * 128 + d)) << 16;
    const float* __restrict__ Rp = g_rightT + plane + i0;
    const float* __restrict__ Lp = g_leftT + plane + jj0;
    float* __restrict__ Mp = g_mixT + plane;

    float acc[2][8][4];
    zacc2(acc);

    cp_tile32(sA[0], Rp, tid);
    cp_tile32(sB[0], Lp, tid);
    CP_COMMIT;

#pragma unroll 1
    for (int k = 0; k < 8; ++k) {
        if (k < 7) {
            cp_tile32(sA[(k + 1) & 1], Rp + (k + 1) * 32 * 256, tid);
            cp_tile32(sB[(k + 1) & 1], Lp + (k + 1) * 32 * 256, tid);
            CP_COMMIT;
            asm volatile("cp.async.wait_group 1;\n");
        } else {
            asm volatile("cp.async.wait_group 0;\n");
        }
        __syncthreads();
        gemm_kT32(sA[k & 1], sB[k & 1], acc, m_base, n_base, g, tg);
        __syncthreads();
    }

#pragma unroll
    for (int mt = 0; mt < 2; ++mt) {
        int row = m_base + mt * 16 + g;
#pragma unroll
        for (int nt = 0; nt < 8; ++nt) {
            int cn = n_base + nt * 8 + tg * 2;
            float2 p0 = {acc[mt][nt][0], acc[mt][nt][1]};
            float2 p1 = {acc[mt][nt][2], acc[mt][nt][3]};
            *reinterpret_cast<float2*>(Mp + (i0 + row) * 256 + jj0 + cn) = p0;
            *reinterpret_cast<float2*>(Mp + (i0 + row + 8) * 256 + jj0 + cn) = p1;
        }
    }
}

// -------------------- Kernel 3: LN(mixed) * ogate @ w_out + b_out (64-row tiles) ----------
__global__ void __launch_bounds__(256, 2) k_post(
    const float* __restrict__ ong, const float* __restrict__ onb,
    const float* __restrict__ wO, const float* __restrict__ bO,
    float* __restrict__ out) {
    extern __shared__ float smemf[];
    float* sx = smemf;                 // 64 x LDP
    float* sw = smemf + 64 * LDP;      // 128 x WLD

    const int tid = threadIdx.x, lane = tid & 31, warp = tid >> 5;
    const int g = lane >> 2, tg = lane & 3;
    const int r0 = blockIdx.x << 6;
    const int b = r0 >> 16, irow = (r0 >> 8) & 255, j0 = r0 & 255;
    const int m_base = (warp >> 2) * 32, n_base = (warp & 3) * 32;

    loadW4<256>(sw, wO, tid);

    for (int i = tid; i < 2048; i += 256) {
        int d = i >> 4, seg = (i & 15) << 2;
        float4 v = __ldg(reinterpret_cast<const float4*>(
            g_mixT + (((size_t)(b * 128 + d)) << 16) + irow * 256 + j0 + seg));
        sx[(seg + 0) * LDP + d] = v.x;
        sx[(seg + 1) * LDP + d] = v.y;
        sx[(seg + 2) * LDP + d] = v.z;
        sx[(seg + 3) * LDP + d] = v.w;
    }
    __syncthreads();

    float og_[4], ob_[4];
#pragma unroll
    for (int q_ = 0; q_ < 4; q_++) {
        og_[q_] = ong[lane + 32 * q_];
        ob_[q_] = onb[lane + 32 * q_];
    }
    for (int row = warp * 8; row < warp * 8 + 8; ++row) {
        float v[4];
#pragma unroll
        for (int q_ = 0; q_ < 4; q_++) v[q_] = sx[row * LDP + lane + 32 * q_];
        float s = v[0] + v[1] + v[2] + v[3];
        float q = fmaf(v[0], v[0], fmaf(v[1], v[1], fmaf(v[2], v[2], v[3] * v[3])));
#pragma unroll
        for (int o = 16; o; o >>= 1) {
            s += __shfl_xor_sync(0xffffffffu, s, o);
            q += __shfl_xor_sync(0xffffffffu, q, o);
        }
        float mu = s * 0.0078125f;
        float rs = rsqrtf(fmaf(-mu, mu, q * 0.0078125f) + 1e-5f);
        const float* gate = g_ogate + ((size_t)(r0 + row)) * 128;
#pragma unroll
        for (int q_ = 0; q_ < 4; q_++) {
            float y = fmaf((v[q_] - mu) * rs, og_[q_], ob_[q_]) * gate[lane + 32 * q_];
            sx[row * LDP + lane + 32 * q_] = to_tf32(y);
        }
    }
    __syncthreads();

    float acc[2][4][4];
    zacc2(acc);
    gemm_rowA<4, LDP>(sx, sw, acc, m_base, n_base, g, tg);

#pragma unroll
    for (int mt = 0; mt < 2; ++mt) {
        int row = m_base + mt * 16 + g;
#pragma unroll
        for (int nt = 0; nt < 4; ++nt) {
            int cn = n_base + nt * 8 + tg * 2;
            float b0v = bO[cn], b1v = bO[cn + 1];
            float2 p0 = {acc[mt][nt][0] + b0v, acc[mt][nt][1] + b1v};
            float2 p1 = {acc[mt][nt][2] + b0v, acc[mt][nt][3] + b1v};
            *reinterpret_cast<float2*>(out + ((size_t)(r0 + row)) * 128 + cn) = p0;
            *reinterpret_cast<float2*>(out + ((size_t)(r0 + row + 8)) * 128 + cn) = p1;
        }
    }
}

extern "C" void kernel_launch(void* const* d_in, const int* in_sizes, int n_in,
                              void* d_out, int out_size) {
    const float* x    = (const float*)d_in[0];
    const float* ng   = (const float*)d_in[1];
    const float* nb   = (const float*)d_in[2];
    const float* wL   = (const float*)d_in[3];
    const float* bL   = (const float*)d_in[4];
    const float* wR   = (const float*)d_in[5];
    const float* bR   = (const float*)d_in[6];
    const float* wLG  = (const float*)d_in[7];
    const float* bLG  = (const float*)d_in[8];
    const float* wRG  = (const float*)d_in[9];
    const float* bRG  = (const float*)d_in[10];
    const float* wOG  = (const float*)d_in[11];
    const float* bOG  = (const float*)d_in[12];
    const float* ong  = (const float*)d_in[13];
    const float* onb  = (const float*)d_in[14];
    const float* wO   = (const float*)d_in[15];
    const float* bO   = (const float*)d_in[16];
    float* out = (float*)d_out;

    cudaFuncSetAttribute(k_pre,  cudaFuncAttributeMaxDynamicSharedMemorySize, SMEM_PRE);
    cudaFuncSetAttribute(k_mix,  cudaFuncAttributeMaxDynamicSharedMemorySize, SMEM_MIX);
    cudaFuncSetAttribute(k_post, cudaFuncAttributeMaxDynamicSharedMemorySize, SMEM_POST);

    k_pre<<<2048, 1024, SMEM_PRE>>>(x, ng, nb, wL, bL, wR, bR, wLG, bLG, wRG, bRG, wOG, bOG);
    k_mix<<<dim3(4, 128, 4), 256, SMEM_MIX>>>();
    k_post<<<4096, 256, SMEM_POST>>>(ong, onb, wO, bO, out);
}

// round 11
// speedup vs baseline: 1.0886x; 1.0886x over previous
#include <cuda_runtime.h>
#include <cuda_fp16.h>
#include <cstdint>

// x [4,256,256,128], DIM=HID=128, R = 262144 rows.
constexpr int LDA = 132;   // k_pre activation tile ld: conflict-free
constexpr int LDP = 133;   // k_post activation tile ld
constexpr int WLD = 136;   // k_pre/k_post weight tiles: banks 8*tg+g, conflict-free
constexpr int WLDH = 272;  // k_mix fp16 tile: halves per kp-row (544B -> banks 8*tg+g)

constexpr int SMEM_PRE  = (128 * LDA + 2 * 128 * WLD) * 4;  // 206,848
constexpr int SMEM_MIX  = 4 * 32 * WLDH * 2;                // 69,632 (2-stage, K-chunk 64)
constexpr int SMEM_POST = (64 * LDP + 128 * WLD) * 4;       // 103,680

// Scratch (device globals). left/right reused as fp16 (needs 64MB of the 134MB).
__device__ float g_leftT [33554432];  // halves: [b][d][k/2][j][2]
__device__ float g_rightT[33554432];  // halves: [b][d][k/2][i][2]
__device__ float g_ogate [33554432];  // [r][d] fp32
__device__ float g_mixT  [33554432];  // [b][d][i][j] fp32

__device__ __forceinline__ float to_tf32(float x) {
    float r;
    asm("cvt.rna.tf32.f32 %0, %1;" : "=f"(r) : "f"(x));
    return r;
}
__device__ __forceinline__ float sigm(float x) { return 1.0f / (1.0f + __expf(-x)); }

__device__ __forceinline__ void mma8(float c[4], const uint32_t a[4], uint32_t b0, uint32_t b1) {
    asm volatile(
        "mma.sync.aligned.m16n8k8.row.col.f32.tf32.tf32.f32 "
        "{%0,%1,%2,%3},{%4,%5,%6,%7},{%8,%9},{%0,%1,%2,%3};\n"
        : "+f"(c[0]), "+f"(c[1]), "+f"(c[2]), "+f"(c[3])
        : "r"(a[0]), "r"(a[1]), "r"(a[2]), "r"(a[3]), "r"(b0), "r"(b1));
}
__device__ __forceinline__ void mma16(float c[4], const uint32_t a[4], uint32_t b0, uint32_t b1) {
    asm volatile(
        "mma.sync.aligned.m16n8k16.row.col.f32.f16.f16.f32 "
        "{%0,%1,%2,%3},{%4,%5,%6,%7},{%8,%9},{%0,%1,%2,%3};\n"
        : "+f"(c[0]), "+f"(c[1]), "+f"(c[2]), "+f"(c[3])
        : "r"(a[0]), "r"(a[1]), "r"(a[2]), "r"(a[3]), "r"(b0), "r"(b1));
}

template <int NT>
__device__ __forceinline__ void zacc2(float (&a)[2][NT][4]) {
#pragma unroll
    for (int i = 0; i < 2; i++)
#pragma unroll
        for (int j = 0; j < NT; j++)
#pragma unroll
            for (int k = 0; k < 4; k++) a[i][j][k] = 0.f;
}

// ---- k_pre dual GEMM: A(row-major ld=LDA) shared, two B's. Warp tile 32 x NT*8 ----
template <int NT>
__device__ __forceinline__ void gemm_dual(const float* __restrict__ sa,
                                          const float* __restrict__ wA,
                                          const float* __restrict__ wB,
                                          float (&acc1)[2][NT][4], float (&acc2)[2][NT][4],
                                          int m_base, int n_base, int g, int tg) {
#pragma unroll
    for (int kk = 0; kk < 128; kk += 8) {
        uint32_t a[2][4];
#pragma unroll
        for (int mt = 0; mt < 2; ++mt) {
            int r = m_base + mt * 16;
            a[mt][0] = __float_as_uint(sa[(r + g) * LDA + kk + tg]);
            a[mt][1] = __float_as_uint(sa[(r + 8 + g) * LDA + kk + tg]);
            a[mt][2] = __float_as_uint(sa[(r + g) * LDA + kk + 4 + tg]);
            a[mt][3] = __float_as_uint(sa[(r + 8 + g) * LDA + kk + 4 + tg]);
        }
#pragma unroll
        for (int nt = 0; nt < NT; ++nt) {
            int cn = n_base + nt * 8 + g;
            uint32_t b00 = __float_as_uint(wA[(kk + tg) * WLD + cn]);
            uint32_t b01 = __float_as_uint(wA[(kk + 4 + tg) * WLD + cn]);
            uint32_t b10 = __float_as_uint(wB[(kk + tg) * WLD + cn]);
            uint32_t b11 = __float_as_uint(wB[(kk + 4 + tg) * WLD + cn]);
            mma8(acc1[0][nt], a[0], b00, b01);
            mma8(acc1[1][nt], a[1], b00, b01);
            mma8(acc2[0][nt], a[0], b10, b11);
            mma8(acc2[1][nt], a[1], b10, b11);
        }
    }
}

template <int NT, int LD>
__device__ __forceinline__ void gemm_rowA(const float* __restrict__ sa,
                                          const float* __restrict__ sw,
                                          float (&acc)[2][NT][4],
                                          int m_base, int n_base, int g, int tg) {
#pragma unroll
    for (int kk = 0; kk < 128; kk += 8) {
        uint32_t a[2][4];
#pragma unroll
        for (int mt = 0; mt < 2; ++mt) {
            int r = m_base + mt * 16;
            a[mt][0] = __float_as_uint(sa[(r + g) * LD + kk + tg]);
            a[mt][1] = __float_as_uint(sa[(r + 8 + g) * LD + kk + tg]);
            a[mt][2] = __float_as_uint(sa[(r + g) * LD + kk + 4 + tg]);
            a[mt][3] = __float_as_uint(sa[(r + 8 + g) * LD + kk + 4 + tg]);
        }
#pragma unroll
        for (int nt = 0; nt < NT; ++nt) {
            int cn = n_base + nt * 8 + g;
            uint32_t b0 = __float_as_uint(sw[(kk + tg) * WLD + cn]);
            uint32_t b1 = __float_as_uint(sw[(kk + 4 + tg) * WLD + cn]);
            mma8(acc[0][nt], a[0], b0, b1);
            mma8(acc[1][nt], a[1], b0, b1);
        }
    }
}

// ---- k_mix fp16 GEMM over one K=64 chunk (32 kp rows in smem, ld=WLDH halves) ----
__device__ __forceinline__ void gemm_h64(const __half* __restrict__ sa,
                                         const __half* __restrict__ sb,
                                         float (&acc)[2][8][4],
                                         int m_base, int n_base, int g, int tg) {
#pragma unroll
    for (int ks = 0; ks < 4; ++ks) {       // K=16 per step
        const int kp0 = ks * 8;
        uint32_t a[2][4];
#pragma unroll
        for (int mt = 0; mt < 2; ++mt) {
            int ib = m_base + mt * 16;
            a[mt][0] = *reinterpret_cast<const uint32_t*>(sa + (kp0 + tg) * WLDH + (ib + g) * 2);
            a[mt][1] = *reinterpret_cast<const uint32_t*>(sa + (kp0 + tg) * WLDH + (ib + 8 + g) * 2);
            a[mt][2] = *reinterpret_cast<const uint32_t*>(sa + (kp0 + tg + 4) * WLDH + (ib + g) * 2);
            a[mt][3] = *reinterpret_cast<const uint32_t*>(sa + (kp0 + tg + 4) * WLDH + (ib + 8 + g) * 2);
        }
#pragma unroll
        for (int nt = 0; nt < 8; ++nt) {
            int cn = n_base + nt * 8 + g;
            uint32_t b0 = *reinterpret_cast<const uint32_t*>(sb + (kp0 + tg) * WLDH + cn * 2);
            uint32_t b1 = *reinterpret_cast<const uint32_t*>(sb + (kp0 + tg + 4) * WLDH + cn * 2);
            mma16(acc[0][nt], a[0], b0, b1);
            mma16(acc[1][nt], a[1], b0, b1);
        }
    }
}

// Vectorized weight load + tf32 round into smem [k][n] (ld=WLD)
template <int NTHR>
__device__ __forceinline__ void loadW4(float* __restrict__ sw, const float* __restrict__ W, int tid) {
    for (int i = tid; i < 4096; i += NTHR) {
        float4 v = __ldg(reinterpret_cast<const float4*>(W) + i);
        float* d = sw + (i >> 5) * WLD + ((i & 31) << 2);
        float4 o = {to_tf32(v.x), to_tf32(v.y), to_tf32(v.z), to_tf32(v.w)};
        *reinterpret_cast<float4*>(d) = o;
    }
}

// combine + direct fp16 writeout to interleaved [d][k/2][j][2] halves
template <int NT>
__device__ __forceinline__ void combine_direct_h(__half* __restrict__ dstT, int krow, int j0,
                                                 const float (&acc1)[2][NT][4], const float (&acc2)[2][NT][4],
                                                 const float* __restrict__ blin, const float* __restrict__ bgat,
                                                 int m_base, int n_base, int g, int tg) {
    const size_t rowoff = (size_t)(krow >> 1) * 512 + (size_t)(krow & 1);
#pragma unroll
    for (int mt = 0; mt < 2; ++mt) {
        int j = j0 + m_base + mt * 16 + g;
#pragma unroll
        for (int nt = 0; nt < NT; ++nt) {
            int d0 = n_base + nt * 8 + tg * 2;
            float bl0 = blin[d0], bl1 = blin[d0 + 1];
            float bg0 = bgat[d0], bg1 = bgat[d0 + 1];
            __half v00 = __float2half_rn((acc1[mt][nt][0] + bl0) * sigm(acc2[mt][nt][0] + bg0));
            __half v01 = __float2half_rn((acc1[mt][nt][1] + bl1) * sigm(acc2[mt][nt][1] + bg1));
            __half v10 = __float2half_rn((acc1[mt][nt][2] + bl0) * sigm(acc2[mt][nt][2] + bg0));
            __half v11 = __float2half_rn((acc1[mt][nt][3] + bl1) * sigm(acc2[mt][nt][3] + bg1));
            __half* p0 = dstT + (((size_t)d0) << 16) + rowoff + (size_t)j * 2;
            __half* p1 = dstT + (((size_t)(d0 + 1)) << 16) + rowoff + (size_t)j * 2;
            p0[0]  = v00;  p1[0]  = v01;
            p0[16] = v10;  p1[16] = v11;   // j+8 -> +16 halves
        }
    }
}

// ----- Kernel 1: LN + 5 projections (R9 structure, fp16 left/right writeout) -----
__global__ void __launch_bounds__(1024, 1) k_pre(
    const float* __restrict__ x, const float* __restrict__ ng, const float* __restrict__ nb,
    const float* __restrict__ wL, const float* __restrict__ bL,
    const float* __restrict__ wR, const float* __restrict__ bR,
    const float* __restrict__ wLG, const float* __restrict__ bLG,
    const float* __restrict__ wRG, const float* __restrict__ bRG,
    const float* __restrict__ wOG, const float* __restrict__ bOG) {
    extern __shared__ float smem[];
    float* sx = smem;                      // 128 x LDA
    float* w0 = smem + 128 * LDA;          // 128 x WLD
    float* w1 = w0 + 128 * WLD;            // 128 x WLD

    const int tid = threadIdx.x, lane = tid & 31, warp = tid >> 5;
    const int g = lane >> 2, tg = lane & 3;
    const int r0 = blockIdx.x << 7;
    const int b = r0 >> 16, krow = (r0 >> 8) & 255, j0 = r0 & 255;
    const int m_base = (warp >> 3) * 32, n_base = (warp & 7) * 16;
    const size_t plane = ((size_t)b * 128) << 16;   // in halves

    loadW4<1024>(w0, wL, tid);
    loadW4<1024>(w1, wLG, tid);
    {
        float4 g4 = reinterpret_cast<const float4*>(ng)[lane];
        float4 b4 = reinterpret_cast<const float4*>(nb)[lane];
        for (int row = warp * 4; row < warp * 4 + 4; ++row) {
            float4 v = reinterpret_cast<const float4*>(x + ((size_t)(r0 + row)) * 128)[lane];
            float s = v.x + v.y + v.z + v.w;
            float q = fmaf(v.x, v.x, fmaf(v.y, v.y, fmaf(v.z, v.z, v.w * v.w)));
#pragma unroll
            for (int o = 16; o; o >>= 1) {
                s += __shfl_xor_sync(0xffffffffu, s, o);
                q += __shfl_xor_sync(0xffffffffu, q, o);
            }
            float mu = s * 0.0078125f;
            float rs = rsqrtf(fmaf(-mu, mu, q * 0.0078125f) + 1e-5f);
            float4 o4 = {to_tf32(fmaf((v.x - mu) * rs, g4.x, b4.x)),
                         to_tf32(fmaf((v.y - mu) * rs, g4.y, b4.y)),
                         to_tf32(fmaf((v.z - mu) * rs, g4.z, b4.z)),
                         to_tf32(fmaf((v.w - mu) * rs, g4.w, b4.w))};
            *reinterpret_cast<float4*>(sx + row * LDA + lane * 4) = o4;
        }
    }
    __syncthreads();

    float acc1[2][2][4], acc2[2][2][4];

    // left pair + per-warp direct fp16 writeout
    zacc2(acc1); zacc2(acc2);
    gemm_dual<2>(sx, w0, w1, acc1, acc2, m_base, n_base, g, tg);
    combine_direct_h<2>(reinterpret_cast<__half*>(g_leftT) + plane, krow, j0,
                        acc1, acc2, bL, bLG, m_base, n_base, g, tg);
    __syncthreads();

    loadW4<1024>(w0, wR, tid);
    loadW4<1024>(w1, wRG, tid);
    __syncthreads();

    // right pair + writeout
    zacc2(acc1); zacc2(acc2);
    gemm_dual<2>(sx, w0, w1, acc1, acc2, m_base, n_base, g, tg);
    combine_direct_h<2>(reinterpret_cast<__half*>(g_rightT) + plane, krow, j0,
                        acc1, acc2, bR, bRG, m_base, n_base, g, tg);
    __syncthreads();

    loadW4<1024>(w0, wOG, tid);
    __syncthreads();

    // ogate gemm + row-major epilogue
    zacc2(acc2);
    gemm_rowA<2, LDA>(sx, w0, acc2, m_base, n_base, g, tg);
#pragma unroll
    for (int mt = 0; mt < 2; ++mt) {
        int row = m_base + mt * 16 + g;
#pragma unroll
        for (int nt = 0; nt < 2; ++nt) {
            int cn = n_base + nt * 8 + tg * 2;
            float bg0 = bOG[cn], bg1 = bOG[cn + 1];
            float2 p0 = {sigm(acc2[mt][nt][0] + bg0), sigm(acc2[mt][nt][1] + bg1)};
            float2 p1 = {sigm(acc2[mt][nt][2] + bg0), sigm(acc2[mt][nt][3] + bg1)};
            *reinterpret_cast<float2*>(g_ogate + ((size_t)(r0 + row)) * 128 + cn) = p0;
            *reinterpret_cast<float2*>(g_ogate + ((size_t)(r0 + row + 8)) * 128 + cn) = p1;
        }
    }
}

// -------------------- Kernel 2: fp16 triangle einsum (2-stage, K-chunk 64) ---------------
__device__ __forceinline__ void cp_tile_h(__half* __restrict__ sdst, const __half* __restrict__ gsrc, int tid) {
    // 32 kp-rows x 512B (gmem row stride 512 halves) -> smem rows stride WLDH halves
#pragma unroll
    for (int m = 0; m < 4; ++m) {
        int i = tid + m * 256;
        int row = i >> 5, seg = (i & 31) * 8;   // 8 halves = 16B
        uint32_t dst = (uint32_t)__cvta_generic_to_shared(sdst + row * WLDH + seg);
        asm volatile("cp.async.ca.shared.global [%0], [%1], 16;\n"
                     :: "r"(dst), "l"(gsrc + row * 512 + seg));
    }
}
#define CP_COMMIT asm volatile("cp.async.commit_group;\n")

__global__ void __launch_bounds__(256, 2) k_mix() {
    extern __shared__ __half smemh[];
    __half* sA[2] = {smemh, smemh + 32 * WLDH};
    __half* sB[2] = {smemh + 2 * 32 * WLDH, smemh + 3 * 32 * WLDH};

    const int tid = threadIdx.x, lane = tid & 31, warp = tid >> 5;
    const int g = lane >> 2, tg = lane & 3;
    const int b = blockIdx.z, d = blockIdx.y;
    const int i0 = (blockIdx.x >> 1) << 7, jj0 = (blockIdx.x & 1) << 7;
    const int m_base = (warp >> 1) * 32, n_base = (warp & 1) * 64;

    const size_t plane = ((size_t)(b * 128 + d)) << 16;  // halves
    const __half* __restrict__ Rp = reinterpret_cast<const __half*>(g_rightT) + plane + i0 * 2;
    const __half* __restrict__ Lp = reinterpret_cast<const __half*>(g_leftT) + plane + jj0 * 2;
    float* __restrict__ Mp = g_mixT + plane;             // fp32 plane (same element count)

    float acc[2][8][4];
    zacc2(acc);

    cp_tile_h(sA[0], Rp, tid);
    cp_tile_h(sB[0], Lp, tid);
    CP_COMMIT;

#pragma unroll 1
    for (int k = 0; k < 4; ++k) {     // 4 chunks of K=64 (32 kp rows, gmem offset 16384 halves)
        if (k < 3) {
            cp_tile_h(sA[(k + 1) & 1], Rp + (size_t)(k + 1) * 16384, tid);
            cp_tile_h(sB[(k + 1) & 1], Lp + (size_t)(k + 1) * 16384, tid);
            CP_COMMIT;
            asm volatile("cp.async.wait_group 1;\n");
        } else {
            asm volatile("cp.async.wait_group 0;\n");
        }
        __syncthreads();
        gemm_h64(sA[k & 1], sB[k & 1], acc, m_base, n_base, g, tg);
        __syncthreads();
    }

#pragma unroll
    for (int mt = 0; mt < 2; ++mt) {
        int row = m_base + mt * 16 + g;
#pragma unroll
        for (int nt = 0; nt < 8; ++nt) {
            int cn = n_base + nt * 8 + tg * 2;
            float2 p0 = {acc[mt][nt][0], acc[mt][nt][1]};
            float2 p1 = {acc[mt][nt][2], acc[mt][nt][3]};
            *reinterpret_cast<float2*>(Mp + (i0 + row) * 256 + jj0 + cn) = p0;
            *reinterpret_cast<float2*>(Mp + (i0 + row + 8) * 256 + jj0 + cn) = p1;
        }
    }
}

// -------------------- Kernel 3: LN(mixed) * ogate @ w_out + b_out (64-row tiles) ----------
__global__ void __launch_bounds__(256, 2) k_post(
    const float* __restrict__ ong, const float* __restrict__ onb,
    const float* __restrict__ wO, const float* __restrict__ bO,
    float* __restrict__ out) {
    extern __shared__ float smemf[];
    float* sx = smemf;                 // 64 x LDP
    float* sw = smemf + 64 * LDP;      // 128 x WLD

    const int tid = threadIdx.x, lane = tid & 31, warp = tid >> 5;
    const int g = lane >> 2, tg = lane & 3;
    const int r0 = blockIdx.x << 6;
    const int b = r0 >> 16, irow = (r0 >> 8) & 255, j0 = r0 & 255;
    const int m_base = (warp >> 2) * 32, n_base = (warp & 3) * 32;

    loadW4<256>(sw, wO, tid);

    for (int i = tid; i < 2048; i += 256) {
        int d = i >> 4, seg = (i & 15) << 2;
        float4 v = __ldg(reinterpret_cast<const float4*>(
            g_mixT + (((size_t)(b * 128 + d)) << 16) + irow * 256 + j0 + seg));
        sx[(seg + 0) * LDP + d] = v.x;
        sx[(seg + 1) * LDP + d] = v.y;
        sx[(seg + 2) * LDP + d] = v.z;
        sx[(seg + 3) * LDP + d] = v.w;
    }
    __syncthreads();

    float og_[4], ob_[4];
#pragma unroll
    for (int q_ = 0; q_ < 4; q_++) {
        og_[q_] = ong[lane + 32 * q_];
        ob_[q_] = onb[lane + 32 * q_];
    }
    for (int row = warp * 8; row < warp * 8 + 8; ++row) {
        float v[4];
#pragma unroll
        for (int q_ = 0; q_ < 4; q_++) v[q_] = sx[row * LDP + lane + 32 * q_];
        float s = v[0] + v[1] + v[2] + v[3];
        float q = fmaf(v[0], v[0], fmaf(v[1], v[1], fmaf(v[2], v[2], v[3] * v[3])));
#pragma unroll
        for (int o = 16; o; o >>= 1) {
            s += __shfl_xor_sync(0xffffffffu, s, o);
            q += __shfl_xor_sync(0xffffffffu, q, o);
        }
        float mu = s * 0.0078125f;
        float rs = rsqrtf(fmaf(-mu, mu, q * 0.0078125f) + 1e-5f);
        const float* gate = g_ogate + ((size_t)(r0 + row)) * 128;
#pragma unroll
        for (int q_ = 0; q_ < 4; q_++) {
            float y = fmaf((v[q_] - mu) * rs, og_[q_], ob_[q_]) * gate[lane + 32 * q_];
            sx[row * LDP + lane + 32 * q_] = to_tf32(y);
        }
    }
    __syncthreads();

    float acc[2][4][4];
    zacc2(acc);
    gemm_rowA<4, LDP>(sx, sw, acc, m_base, n_base, g, tg);

#pragma unroll
    for (int mt = 0; mt < 2; ++mt) {
        int row = m_base + mt * 16 + g;
#pragma unroll
        for (int nt = 0; nt < 4; ++nt) {
            int cn = n_base + nt * 8 + tg * 2;
            float b0v = bO[cn], b1v = bO[cn + 1];
            float2 p0 = {acc[mt][nt][0] + b0v, acc[mt][nt][1] + b1v};
            float2 p1 = {acc[mt][nt][2] + b0v, acc[mt][nt][3] + b1v};
            *reinterpret_cast<float2*>(out + ((size_t)(r0 + row)) * 128 + cn) = p0;
            *reinterpret_cast<float2*>(out + ((size_t)(r0 + row + 8)) * 128 + cn) = p1;
        }
    }
}

extern "C" void kernel_launch(void* const* d_in, const int* in_sizes, int n_in,
                              void* d_out, int out_size) {
    const float* x    = (const float*)d_in[0];
    const float* ng   = (const float*)d_in[1];
    const float* nb   = (const float*)d_in[2];
    const float* wL   = (const float*)d_in[3];
    const float* bL   = (const float*)d_in[4];
    const float* wR   = (const float*)d_in[5];
    const float* bR   = (const float*)d_in[6];
    const float* wLG  = (const float*)d_in[7];
    const float* bLG  = (const float*)d_in[8];
    const float* wRG  = (const float*)d_in[9];
    const float* bRG  = (const float*)d_in[10];
    const float* wOG  = (const float*)d_in[11];
    const float* bOG  = (const float*)d_in[12];
    const float* ong  = (const float*)d_in[13];
    const float* onb  = (const float*)d_in[14];
    const float* wO   = (const float*)d_in[15];
    const float* bO   = (const float*)d_in[16];
    float* out = (float*)d_out;

    cudaFuncSetAttribute(k_pre,  cudaFuncAttributeMaxDynamicSharedMemorySize, SMEM_PRE);
    cudaFuncSetAttribute(k_mix,  cudaFuncAttributeMaxDynamicSharedMemorySize, SMEM_MIX);
    cudaFuncSetAttribute(k_post, cudaFuncAttributeMaxDynamicSharedMemorySize, SMEM_POST);

    k_pre<<<2048, 1024, SMEM_PRE>>>(x, ng, nb, wL, bL, wR, bR, wLG, bLG, wRG, bRG, wOG, bOG);
    k_mix<<<dim3(4, 128, 4), 256, SMEM_MIX>>>();
    k_post<<<4096, 256, SMEM_POST>>>(ong, onb, wO, bO, out);
}

// round 13
// speedup vs baseline: 1.3519x; 1.2419x over previous
#include <cuda_runtime.h>
#include <cuda_fp16.h>
#include <cstdint>

// x [4,256,256,128], DIM=HID=128, R = 262144 rows.
constexpr int LDP  = 133;  // k_post activation tile ld (fp32)
constexpr int WLD  = 136;  // k_post weight tile (fp32)
constexpr int LDAH = 136;  // k_pre fp16 activation ld in halves (272B; 272%128==16 -> CF)
constexpr int WLDH = 272;  // fp16 k-pair tiles: halves per kp-row (544B; %128==32 -> CF)

constexpr int SMEM_PRE  = (128 * LDAH + 2 * 64 * WLDH) * 2;  // 104,448
constexpr int SMEM_MIX  = 4 * 32 * WLDH * 2;                 // 69,632
constexpr int SMEM_POST = (64 * LDP + 128 * WLD) * 4;        // 103,680

// Scratch (device globals). left/right stored as fp16 halves.
__device__ float g_leftT [33554432];  // halves: [b][d][k/2][j][2]
__device__ float g_rightT[33554432];  // halves: [b][d][k/2][i][2]
__device__ float g_ogate [33554432];  // [r][d] fp32
__device__ float g_mixT  [33554432];  // [b][d][i][j] fp32

__device__ __forceinline__ uint32_t h2u(__half2 h) {
    return *reinterpret_cast<uint32_t*>(&h);
}

__device__ __forceinline__ float to_tf32(float x) {
    float r;
    asm("cvt.rna.tf32.f32 %0, %1;" : "=f"(r) : "f"(x));
    return r;
}
__device__ __forceinline__ float sigm(float x) { return 1.0f / (1.0f + __expf(-x)); }

__device__ __forceinline__ void mma8(float c[4], const uint32_t a[4], uint32_t b0, uint32_t b1) {
    asm volatile(
        "mma.sync.aligned.m16n8k8.row.col.f32.tf32.tf32.f32 "
        "{%0,%1,%2,%3},{%4,%5,%6,%7},{%8,%9},{%0,%1,%2,%3};\n"
        : "+f"(c[0]), "+f"(c[1]), "+f"(c[2]), "+f"(c[3])
        : "r"(a[0]), "r"(a[1]), "r"(a[2]), "r"(a[3]), "r"(b0), "r"(b1));
}
__device__ __forceinline__ void mma16(float c[4], const uint32_t a[4], uint32_t b0, uint32_t b1) {
    asm volatile(
        "mma.sync.aligned.m16n8k16.row.col.f32.f16.f16.f32 "
        "{%0,%1,%2,%3},{%4,%5,%6,%7},{%8,%9},{%0,%1,%2,%3};\n"
        : "+f"(c[0]), "+f"(c[1]), "+f"(c[2]), "+f"(c[3])
        : "r"(a[0]), "r"(a[1]), "r"(a[2]), "r"(a[3]), "r"(b0), "r"(b1));
}

template <int NT>
__device__ __forceinline__ void zacc2(float (&a)[2][NT][4]) {
#pragma unroll
    for (int i = 0; i < 2; i++)
#pragma unroll
        for (int j = 0; j < NT; j++)
#pragma unroll
            for (int k = 0; k < 4; k++) a[i][j][k] = 0.f;
}

// ---- k_pre fp16 dual GEMM: A row-major fp16 (ld=LDAH halves), B [kp][n][2] ----
template <int NT>
__device__ __forceinline__ void gemm_dual_h(const __half* __restrict__ sa,
                                            const __half* __restrict__ wA,
                                            const __half* __restrict__ wB,
                                            float (&acc1)[2][NT][4], float (&acc2)[2][NT][4],
                                            int m_base, int n_base, int g, int tg) {
#pragma unroll
    for (int ks = 0; ks < 8; ++ks) {       // K=16 per step
        uint32_t a[2][4];
#pragma unroll
        for (int mt = 0; mt < 2; ++mt) {
            int r = m_base + mt * 16;
            const __half* p0 = sa + (r + g) * LDAH + ks * 16 + tg * 2;
            const __half* p1 = sa + (r + 8 + g) * LDAH + ks * 16 + tg * 2;
            a[mt][0] = *reinterpret_cast<const uint32_t*>(p0);
            a[mt][1] = *reinterpret_cast<const uint32_t*>(p1);
            a[mt][2] = *reinterpret_cast<const uint32_t*>(p0 + 8);
            a[mt][3] = *reinterpret_cast<const uint32_t*>(p1 + 8);
        }
#pragma unroll
        for (int nt = 0; nt < NT; ++nt) {
            int cn = n_base + nt * 8 + g;
            uint32_t b00 = *reinterpret_cast<const uint32_t*>(wA + (ks * 8 + tg) * WLDH + cn * 2);
            uint32_t b01 = *reinterpret_cast<const uint32_t*>(wA + (ks * 8 + 4 + tg) * WLDH + cn * 2);
            uint32_t b10 = *reinterpret_cast<const uint32_t*>(wB + (ks * 8 + tg) * WLDH + cn * 2);
            uint32_t b11 = *reinterpret_cast<const uint32_t*>(wB + (ks * 8 + 4 + tg) * WLDH + cn * 2);
            mma16(acc1[0][nt], a[0], b00, b01);
            mma16(acc1[1][nt], a[1], b00, b01);
            mma16(acc2[0][nt], a[0], b10, b11);
            mma16(acc2[1][nt], a[1], b10, b11);
        }
    }
}

template <int NT>
__device__ __forceinline__ void gemm_single_h(const __half* __restrict__ sa,
                                              const __half* __restrict__ wA,
                                              float (&acc)[2][NT][4],
                                              int m_base, int n_base, int g, int tg) {
#pragma unroll
    for (int ks = 0; ks < 8; ++ks) {
        uint32_t a[2][4];
#pragma unroll
        for (int mt = 0; mt < 2; ++mt) {
            int r = m_base + mt * 16;
            const __half* p0 = sa + (r + g) * LDAH + ks * 16 + tg * 2;
            const __half* p1 = sa + (r + 8 + g) * LDAH + ks * 16 + tg * 2;
            a[mt][0] = *reinterpret_cast<const uint32_t*>(p0);
            a[mt][1] = *reinterpret_cast<const uint32_t*>(p1);
            a[mt][2] = *reinterpret_cast<const uint32_t*>(p0 + 8);
            a[mt][3] = *reinterpret_cast<const uint32_t*>(p1 + 8);
        }
#pragma unroll
        for (int nt = 0; nt < NT; ++nt) {
            int cn = n_base + nt * 8 + g;
            uint32_t b0 = *reinterpret_cast<const uint32_t*>(wA + (ks * 8 + tg) * WLDH + cn * 2);
            uint32_t b1 = *reinterpret_cast<const uint32_t*>(wA + (ks * 8 + 4 + tg) * WLDH + cn * 2);
            mma16(acc[0][nt], a[0], b0, b1);
            mma16(acc[1][nt], a[1], b0, b1);
        }
    }
}

// ---- k_post tf32 GEMM (unchanged) ----
template <int NT, int LD>
__device__ __forceinline__ void gemm_rowA(const float* __restrict__ sa,
                                          const float* __restrict__ sw,
                                          float (&acc)[2][NT][4],
                                          int m_base, int n_base, int g, int tg) {
#pragma unroll
    for (int kk = 0; kk < 128; kk += 8) {
        uint32_t a[2][4];
#pragma unroll
        for (int mt = 0; mt < 2; ++mt) {
            int r = m_base + mt * 16;
            a[mt][0] = __float_as_uint(sa[(r + g) * LD + kk + tg]);
            a[mt][1] = __float_as_uint(sa[(r + 8 + g) * LD + kk + tg]);
            a[mt][2] = __float_as_uint(sa[(r + g) * LD + kk + 4 + tg]);
            a[mt][3] = __float_as_uint(sa[(r + 8 + g) * LD + kk + 4 + tg]);
        }
#pragma unroll
        for (int nt = 0; nt < NT; ++nt) {
            int cn = n_base + nt * 8 + g;
            uint32_t b0 = __float_as_uint(sw[(kk + tg) * WLD + cn]);
            uint32_t b1 = __float_as_uint(sw[(kk + 4 + tg) * WLD + cn]);
            mma8(acc[0][nt], a[0], b0, b1);
            mma8(acc[1][nt], a[1], b0, b1);
        }
    }
}

// ---- k_mix fp16 GEMM over one K=64 chunk ----
__device__ __forceinline__ void gemm_h64(const __half* __restrict__ sa,
                                         const __half* __restrict__ sb,
                                         float (&acc)[2][8][4],
                                         int m_base, int n_base, int g, int tg) {
#pragma unroll
    for (int ks = 0; ks < 4; ++ks) {
        const int kp0 = ks * 8;
        uint32_t a[2][4];
#pragma unroll
        for (int mt = 0; mt < 2; ++mt) {
            int ib = m_base + mt * 16;
            a[mt][0] = *reinterpret_cast<const uint32_t*>(sa + (kp0 + tg) * WLDH + (ib + g) * 2);
            a[mt][1] = *reinterpret_cast<const uint32_t*>(sa + (kp0 + tg) * WLDH + (ib + 8 + g) * 2);
            a[mt][2] = *reinterpret_cast<const uint32_t*>(sa + (kp0 + tg + 4) * WLDH + (ib + g) * 2);
            a[mt][3] = *reinterpret_cast<const uint32_t*>(sa + (kp0 + tg + 4) * WLDH + (ib + 8 + g) * 2);
        }
#pragma unroll
        for (int nt = 0; nt < 8; ++nt) {
            int cn = n_base + nt * 8 + g;
            uint32_t b0 = *reinterpret_cast<const uint32_t*>(sb + (kp0 + tg) * WLDH + cn * 2);
            uint32_t b1 = *reinterpret_cast<const uint32_t*>(sb + (kp0 + tg + 4) * WLDH + cn * 2);
            mma16(acc[0][nt], a[0], b0, b1);
            mma16(acc[1][nt], a[1], b0, b1);
        }
    }
}

// fp32 weight load (k_post)
template <int NTHR>
__device__ __forceinline__ void loadW4(float* __restrict__ sw, const float* __restrict__ W, int tid) {
    for (int i = tid; i < 4096; i += NTHR) {
        float4 v = __ldg(reinterpret_cast<const float4*>(W) + i);
        float* d = sw + (i >> 5) * WLD + ((i & 31) << 2);
        float4 o = {to_tf32(v.x), to_tf32(v.y), to_tf32(v.z), to_tf32(v.w)};
        *reinterpret_cast<float4*>(d) = o;
    }
}

// fp16 weight load: gmem W[k][n] -> smem [kp][n][2] halves (pairs (k,k+1) per n)
__device__ __forceinline__ void loadW_h(__half* __restrict__ sw, const float* __restrict__ W, int tid) {
#pragma unroll
    for (int it = 0; it < 2; ++it) {
        int idx = tid + it * 1024;            // 2048 items: kp = idx>>5, nq = idx&31
        int kp = idx >> 5, nq = idx & 31;
        float4 v0 = __ldg(reinterpret_cast<const float4*>(W + (kp * 2) * 128) + nq);
        float4 v1 = __ldg(reinterpret_cast<const float4*>(W + (kp * 2 + 1) * 128) + nq);
        uint4 o;
        o.x = h2u(__floats2half2_rn(v0.x, v1.x));
        o.y = h2u(__floats2half2_rn(v0.y, v1.y));
        o.z = h2u(__floats2half2_rn(v0.z, v1.z));
        o.w = h2u(__floats2half2_rn(v0.w, v1.w));
        *reinterpret_cast<uint4*>(sw + kp * WLDH + nq * 8) = o;
    }
}

// combine + direct fp16 writeout to interleaved [d][k/2][j][2] halves
template <int NT>
__device__ __forceinline__ void combine_direct_h(__half* __restrict__ dstT, int krow, int j0,
                                                 const float (&acc1)[2][NT][4], const float (&acc2)[2][NT][4],
                                                 const float* __restrict__ blin, const float* __restrict__ bgat,
                                                 int m_base, int n_base, int g, int tg) {
    const size_t rowoff = (size_t)(krow >> 1) * 512 + (size_t)(krow & 1);
#pragma unroll
    for (int mt = 0; mt < 2; ++mt) {
        int j = j0 + m_base + mt * 16 + g;
#pragma unroll
        for (int nt = 0; nt < NT; ++nt) {
            int d0 = n_base + nt * 8 + tg * 2;
            float bl0 = blin[d0], bl1 = blin[d0 + 1];
            float bg0 = bgat[d0], bg1 = bgat[d0 + 1];
            __half v00 = __float2half_rn((acc1[mt][nt][0] + bl0) * sigm(acc2[mt][nt][0] + bg0));
            __half v01 = __float2half_rn((acc1[mt][nt][1] + bl1) * sigm(acc2[mt][nt][1] + bg1));
            __half v10 = __float2half_rn((acc1[mt][nt][2] + bl0) * sigm(acc2[mt][nt][2] + bg0));
            __half v11 = __float2half_rn((acc1[mt][nt][3] + bl1) * sigm(acc2[mt][nt][3] + bg1));
            __half* p0 = dstT + (((size_t)d0) << 16) + rowoff + (size_t)j * 2;
            __half* p1 = dstT + (((size_t)(d0 + 1)) << 16) + rowoff + (size_t)j * 2;
            p0[0]  = v00;  p1[0]  = v01;
            p0[16] = v10;  p1[16] = v11;
        }
    }
}

// ----- Kernel 1: LN + 5 projections, full fp16 MMA (1024 thr, 32 warps, tile 32x16) -----
__global__ void __launch_bounds__(1024, 1) k_pre(
    const float* __restrict__ x, const float* __restrict__ ng, const float* __restrict__ nb,
    const float* __restrict__ wL, const float* __restrict__ bL,
    const float* __restrict__ wR, const float* __restrict__ bR,
    const float* __restrict__ wLG, const float* __restrict__ bLG,
    const float* __restrict__ wRG, const float* __restrict__ bRG,
    const float* __restrict__ wOG, const float* __restrict__ bOG) {
    extern __shared__ __half smemh[];
    __half* sx = smemh;                      // 128 x LDAH halves
    __half* w0 = smemh + 128 * LDAH;         // 64 x WLDH halves
    __half* w1 = w0 + 64 * WLDH;

    const int tid = threadIdx.x, lane = tid & 31, warp = tid >> 5;
    const int g = lane >> 2, tg = lane & 3;
    const int r0 = blockIdx.x << 7;
    const int b = r0 >> 16, krow = (r0 >> 8) & 255, j0 = r0 & 255;
    const int m_base = (warp >> 3) * 32, n_base = (warp & 7) * 16;
    const size_t plane = ((size_t)b * 128) << 16;   // halves

    loadW_h(w0, wL, tid);
    loadW_h(w1, wLG, tid);
    {
        float4 g4 = reinterpret_cast<const float4*>(ng)[lane];
        float4 b4 = reinterpret_cast<const float4*>(nb)[lane];
        for (int row = warp * 4; row < warp * 4 + 4; ++row) {
            float4 v = reinterpret_cast<const float4*>(x + ((size_t)(r0 + row)) * 128)[lane];
            float s = v.x + v.y + v.z + v.w;
            float q = fmaf(v.x, v.x, fmaf(v.y, v.y, fmaf(v.z, v.z, v.w * v.w)));
#pragma unroll
            for (int o = 16; o; o >>= 1) {
                s += __shfl_xor_sync(0xffffffffu, s, o);
                q += __shfl_xor_sync(0xffffffffu, q, o);
            }
            float mu = s * 0.0078125f;
            float rs = rsqrtf(fmaf(-mu, mu, q * 0.0078125f) + 1e-5f);
            __half2 h0 = __floats2half2_rn(fmaf((v.x - mu) * rs, g4.x, b4.x),
                                           fmaf((v.y - mu) * rs, g4.y, b4.y));
            __half2 h1 = __floats2half2_rn(fmaf((v.z - mu) * rs, g4.z, b4.z),
                                           fmaf((v.w - mu) * rs, g4.w, b4.w));
            uint2 o2 = {h2u(h0), h2u(h1)};
            *reinterpret_cast<uint2*>(sx + row * LDAH + lane * 4) = o2;
        }
    }
    __syncthreads();

    float acc1[2][2][4], acc2[2][2][4];

    // left pair + per-warp direct fp16 writeout
    zacc2(acc1); zacc2(acc2);
    gemm_dual_h<2>(sx, w0, w1, acc1, acc2, m_base, n_base, g, tg);
    combine_direct_h<2>(reinterpret_cast<__half*>(g_leftT) + plane, krow, j0,
                        acc1, acc2, bL, bLG, m_base, n_base, g, tg);
    __syncthreads();

    loadW_h(w0, wR, tid);
    loadW_h(w1, wRG, tid);
    __syncthreads();

    // right pair + writeout
    zacc2(acc1); zacc2(acc2);
    gemm_dual_h<2>(sx, w0, w1, acc1, acc2, m_base, n_base, g, tg);
    combine_direct_h<2>(reinterpret_cast<__half*>(g_rightT) + plane, krow, j0,
                        acc1, acc2, bR, bRG, m_base, n_base, g, tg);
    __syncthreads();

    loadW_h(w0, wOG, tid);
    __syncthreads();

    // ogate gemm + row-major epilogue
    zacc2(acc2);
    gemm_single_h<2>(sx, w0, acc2, m_base, n_base, g, tg);
#pragma unroll
    for (int mt = 0; mt < 2; ++mt) {
        int row = m_base + mt * 16 + g;
#pragma unroll
        for (int nt = 0; nt < 2; ++nt) {
            int cn = n_base + nt * 8 + tg * 2;
            float bg0 = bOG[cn], bg1 = bOG[cn + 1];
            float2 p0 = {sigm(acc2[mt][nt][0] + bg0), sigm(acc2[mt][nt][1] + bg1)};
            float2 p1 = {sigm(acc2[mt][nt][2] + bg0), sigm(acc2[mt][nt][3] + bg1)};
            *reinterpret_cast<float2*>(g_ogate + ((size_t)(r0 + row)) * 128 + cn) = p0;
            *reinterpret_cast<float2*>(g_ogate + ((size_t)(r0 + row + 8)) * 128 + cn) = p1;
        }
    }
}

// -------------------- Kernel 2: fp16 triangle einsum (2-stage, K-chunk 64) ---------------
__device__ __forceinline__ void cp_tile_h(__half* __restrict__ sdst, const __half* __restrict__ gsrc, int tid) {
#pragma unroll
    for (int m = 0; m < 4; ++m) {
        int i = tid + m * 256;
        int row = i >> 5, seg = (i & 31) * 8;
        uint32_t dst = (uint32_t)__cvta_generic_to_shared(sdst + row * WLDH + seg);
        asm volatile("cp.async.ca.shared.global [%0], [%1], 16;\n"
                     :: "r"(dst), "l"(gsrc + row * 512 + seg));
    }
}
#define CP_COMMIT asm volatile("cp.async.commit_group;\n")

__global__ void __launch_bounds__(256, 2) k_mix() {
    extern __shared__ __half smemh[];
    __half* sA[2] = {smemh, smemh + 32 * WLDH};
    __half* sB[2] = {smemh + 2 * 32 * WLDH, smemh + 3 * 32 * WLDH};

    const int tid = threadIdx.x, lane = tid & 31, warp = tid >> 5;
    const int g = lane >> 2, tg = lane & 3;
    const int b = blockIdx.z, d = blockIdx.y;
    const int i0 = (blockIdx.x >> 1) << 7, jj0 = (blockIdx.x & 1) << 7;
    const int m_base = (warp >> 1) * 32, n_base = (warp & 1) * 64;

    const size_t plane = ((size_t)(b * 128 + d)) << 16;
    const __half* __restrict__ Rp = reinterpret_cast<const __half*>(g_rightT) + plane + i0 * 2;
    const __half* __restrict__ Lp = reinterpret_cast<const __half*>(g_leftT) + plane + jj0 * 2;
    float* __restrict__ Mp = g_mixT + plane;

    float acc[2][8][4];
    zacc2(acc);

    cp_tile_h(sA[0], Rp, tid);
    cp_tile_h(sB[0], Lp, tid);
    CP_COMMIT;

#pragma unroll 1
    for (int k = 0; k < 4; ++k) {
        if (k < 3) {
            cp_tile_h(sA[(k + 1) & 1], Rp + (size_t)(k + 1) * 16384, tid);
            cp_tile_h(sB[(k + 1) & 1], Lp + (size_t)(k + 1) * 16384, tid);
            CP_COMMIT;
            asm volatile("cp.async.wait_group 1;\n");
        } else {
            asm volatile("cp.async.wait_group 0;\n");
        }
        __syncthreads();
        gemm_h64(sA[k & 1], sB[k & 1], acc, m_base, n_base, g, tg);
        __syncthreads();
    }

#pragma unroll
    for (int mt = 0; mt < 2; ++mt) {
        int row = m_base + mt * 16 + g;
#pragma unroll
        for (int nt = 0; nt < 8; ++nt) {
            int cn = n_base + nt * 8 + tg * 2;
            float2 p0 = {acc[mt][nt][0], acc[mt][nt][1]};
            float2 p1 = {acc[mt][nt][2], acc[mt][nt][3]};
            *reinterpret_cast<float2*>(Mp + (i0 + row) * 256 + jj0 + cn) = p0;
            *reinterpret_cast<float2*>(Mp + (i0 + row + 8) * 256 + jj0 + cn) = p1;
        }
    }
}

// -------------------- Kernel 3: LN(mixed) * ogate @ w_out + b_out (64-row tiles) ----------
__global__ void __launch_bounds__(256, 2) k_post(
    const float* __restrict__ ong, const float* __restrict__ onb,
    const float* __restrict__ wO, const float* __restrict__ bO,
    float* __restrict__ out) {
    extern __shared__ float smemf[];
    float* sx = smemf;                 // 64 x LDP
    float* sw = smemf + 64 * LDP;      // 128 x WLD

    const int tid = threadIdx.x, lane = tid & 31, warp = tid >> 5;
    const int g = lane >> 2, tg = lane & 3;
    const int r0 = blockIdx.x << 6;
    const int b = r0 >> 16, irow = (r0 >> 8) & 255, j0 = r0 & 255;
    const int m_base = (warp >> 2) * 32, n_base = (warp & 3) * 32;

    loadW4<256>(sw, wO, tid);

    for (int i = tid; i < 2048; i += 256) {
        int d = i >> 4, seg = (i & 15) << 2;
        float4 v = __ldg(reinterpret_cast<const float4*>(
            g_mixT + (((size_t)(b * 128 + d)) << 16) + irow * 256 + j0 + seg));
        sx[(seg + 0) * LDP + d] = v.x;
        sx[(seg + 1) * LDP + d] = v.y;
        sx[(seg + 2) * LDP + d] = v.z;
        sx[(seg + 3) * LDP + d] = v.w;
    }
    __syncthreads();

    float og_[4], ob_[4];
#pragma unroll
    for (int q_ = 0; q_ < 4; q_++) {
        og_[q_] = ong[lane + 32 * q_];
        ob_[q_] = onb[lane + 32 * q_];
    }
    for (int row = warp * 8; row < warp * 8 + 8; ++row) {
        float v[4];
#pragma unroll
        for (int q_ = 0; q_ < 4; q_++) v[q_] = sx[row * LDP + lane + 32 * q_];
        float s = v[0] + v[1] + v[2] + v[3];
        float q = fmaf(v[0], v[0], fmaf(v[1], v[1], fmaf(v[2], v[2], v[3] * v[3])));
#pragma unroll
        for (int o = 16; o; o >>= 1) {
            s += __shfl_xor_sync(0xffffffffu, s, o);
            q += __shfl_xor_sync(0xffffffffu, q, o);
        }
        float mu = s * 0.0078125f;
        float rs = rsqrtf(fmaf(-mu, mu, q * 0.0078125f) + 1e-5f);
        const float* gate = g_ogate + ((size_t)(r0 + row)) * 128;
#pragma unroll
        for (int q_ = 0; q_ < 4; q_++) {
            float y = fmaf((v[q_] - mu) * rs, og_[q_], ob_[q_]) * gate[lane + 32 * q_];
            sx[row * LDP + lane + 32 * q_] = to_tf32(y);
        }
    }
    __syncthreads();

    float acc[2][4][4];
    zacc2(acc);
    gemm_rowA<4, LDP>(sx, sw, acc, m_base, n_base, g, tg);

#pragma unroll
    for (int mt = 0; mt < 2; ++mt) {
        int row = m_base + mt * 16 + g;
#pragma unroll
        for (int nt = 0; nt < 4; ++nt) {
            int cn = n_base + nt * 8 + tg * 2;
            float b0v = bO[cn], b1v = bO[cn + 1];
            float2 p0 = {acc[mt][nt][0] + b0v, acc[mt][nt][1] + b1v};
            float2 p1 = {acc[mt][nt][2] + b0v, acc[mt][nt][3] + b1v};
            *reinterpret_cast<float2*>(out + ((size_t)(r0 + row)) * 128 + cn) = p0;
            *reinterpret_cast<float2*>(out + ((size_t)(r0 + row + 8)) * 128 + cn) = p1;
        }
    }
}

extern "C" void kernel_launch(void* const* d_in, const int* in_sizes, int n_in,
                              void* d_out, int out_size) {
    const float* x    = (const float*)d_in[0];
    const float* ng   = (const float*)d_in[1];
    const float* nb   = (const float*)d_in[2];
    const float* wL   = (const float*)d_in[3];
    const float* bL   = (const float*)d_in[4];
    const float* wR   = (const float*)d_in[5];
    const float* bR   = (const float*)d_in[6];
    const float* wLG  = (const float*)d_in[7];
    const float* bLG  = (const float*)d_in[8];
    const float* wRG  = (const float*)d_in[9];
    const float* bRG  = (const float*)d_in[10];
    const float* wOG  = (const float*)d_in[11];
    const float* bOG  = (const float*)d_in[12];
    const float* ong  = (const float*)d_in[13];
    const float* onb  = (const float*)d_in[14];
    const float* wO   = (const float*)d_in[15];
    const float* bO   = (const float*)d_in[16];
    float* out = (float*)d_out;

    cudaFuncSetAttribute(k_pre,  cudaFuncAttributeMaxDynamicSharedMemorySize, SMEM_PRE);
    cudaFuncSetAttribute(k_mix,  cudaFuncAttributeMaxDynamicSharedMemorySize, SMEM_MIX);
    cudaFuncSetAttribute(k_post, cudaFuncAttributeMaxDynamicSharedMemorySize, SMEM_POST);

    k_pre<<<2048, 1024, SMEM_PRE>>>(x, ng, nb, wL, bL, wR, bR, wLG, bLG, wRG, bRG, wOG, bOG);
    k_mix<<<dim3(4, 128, 4), 256, SMEM_MIX>>>();
    k_post<<<4096, 256, SMEM_POST>>>(ong, onb, wO, bO, out);
}

// round 14
// speedup vs baseline: 1.6648x; 1.2314x over previous
#include <cuda_runtime.h>
#include <cuda_fp16.h>
#include <cstdint>

// x [4,256,256,128], DIM=HID=128, R = 262144 rows.
constexpr int LDAH = 136;  // fp16 activation ld in halves (272B; %128==16 -> CF)
constexpr int WLDH = 272;  // fp16 k-pair tiles: halves per kp-row (544B; %128==32 -> CF)

constexpr int SMEM_PRE  = (128 * LDAH + 2 * 64 * WLDH) * 2;  // 104,448
constexpr int SMEM_MIX  = 4 * 32 * WLDH * 2;                 // 69,632
constexpr int SMEM_POST = (64 * LDAH + 64 * WLDH) * 2;       // 52,224

// Scratch (device globals). All intermediates fp16 halves.
__device__ float g_leftT [33554432];  // halves: [b][d][k/2][j][2]
__device__ float g_rightT[33554432];  // halves: [b][d][k/2][i][2]
__device__ float g_ogate [16777216];  // halves: [r][d]
__device__ float g_mixT  [16777216];  // halves: [b][d][i][j]

__device__ __forceinline__ uint32_t h2u(__half2 h) {
    return *reinterpret_cast<uint32_t*>(&h);
}
__device__ __forceinline__ float sigm(float x) { return 1.0f / (1.0f + __expf(-x)); }

__device__ __forceinline__ void mma16(float c[4], const uint32_t a[4], uint32_t b0, uint32_t b1) {
    asm volatile(
        "mma.sync.aligned.m16n8k16.row.col.f32.f16.f16.f32 "
        "{%0,%1,%2,%3},{%4,%5,%6,%7},{%8,%9},{%0,%1,%2,%3};\n"
        : "+f"(c[0]), "+f"(c[1]), "+f"(c[2]), "+f"(c[3])
        : "r"(a[0]), "r"(a[1]), "r"(a[2]), "r"(a[3]), "r"(b0), "r"(b1));
}

template <int NT>
__device__ __forceinline__ void zacc2(float (&a)[2][NT][4]) {
#pragma unroll
    for (int i = 0; i < 2; i++)
#pragma unroll
        for (int j = 0; j < NT; j++)
#pragma unroll
            for (int k = 0; k < 4; k++) a[i][j][k] = 0.f;
}

// ---- fp16 dual GEMM: A row-major fp16 (ld=LDAH halves), B [kp][n][2] ----
template <int NT>
__device__ __forceinline__ void gemm_dual_h(const __half* __restrict__ sa,
                                            const __half* __restrict__ wA,
                                            const __half* __restrict__ wB,
                                            float (&acc1)[2][NT][4], float (&acc2)[2][NT][4],
                                            int m_base, int n_base, int g, int tg) {
#pragma unroll
    for (int ks = 0; ks < 8; ++ks) {       // K=16 per step
        uint32_t a[2][4];
#pragma unroll
        for (int mt = 0; mt < 2; ++mt) {
            int r = m_base + mt * 16;
            const __half* p0 = sa + (r + g) * LDAH + ks * 16 + tg * 2;
            const __half* p1 = sa + (r + 8 + g) * LDAH + ks * 16 + tg * 2;
            a[mt][0] = *reinterpret_cast<const uint32_t*>(p0);
            a[mt][1] = *reinterpret_cast<const uint32_t*>(p1);
            a[mt][2] = *reinterpret_cast<const uint32_t*>(p0 + 8);
            a[mt][3] = *reinterpret_cast<const uint32_t*>(p1 + 8);
        }
#pragma unroll
        for (int nt = 0; nt < NT; ++nt) {
            int cn = n_base + nt * 8 + g;
            uint32_t b00 = *reinterpret_cast<const uint32_t*>(wA + (ks * 8 + tg) * WLDH + cn * 2);
            uint32_t b01 = *reinterpret_cast<const uint32_t*>(wA + (ks * 8 + 4 + tg) * WLDH + cn * 2);
            uint32_t b10 = *reinterpret_cast<const uint32_t*>(wB + (ks * 8 + tg) * WLDH + cn * 2);
            uint32_t b11 = *reinterpret_cast<const uint32_t*>(wB + (ks * 8 + 4 + tg) * WLDH + cn * 2);
            mma16(acc1[0][nt], a[0], b00, b01);
            mma16(acc1[1][nt], a[1], b00, b01);
            mma16(acc2[0][nt], a[0], b10, b11);
            mma16(acc2[1][nt], a[1], b10, b11);
        }
    }
}

template <int NT>
__device__ __forceinline__ void gemm_single_h(const __half* __restrict__ sa,
                                              const __half* __restrict__ wA,
                                              float (&acc)[2][NT][4],
                                              int m_base, int n_base, int g, int tg) {
#pragma unroll
    for (int ks = 0; ks < 8; ++ks) {
        uint32_t a[2][4];
#pragma unroll
        for (int mt = 0; mt < 2; ++mt) {
            int r = m_base + mt * 16;
            const __half* p0 = sa + (r + g) * LDAH + ks * 16 + tg * 2;
            const __half* p1 = sa + (r + 8 + g) * LDAH + ks * 16 + tg * 2;
            a[mt][0] = *reinterpret_cast<const uint32_t*>(p0);
            a[mt][1] = *reinterpret_cast<const uint32_t*>(p1);
            a[mt][2] = *reinterpret_cast<const uint32_t*>(p0 + 8);
            a[mt][3] = *reinterpret_cast<const uint32_t*>(p1 + 8);
        }
#pragma unroll
        for (int nt = 0; nt < NT; ++nt) {
            int cn = n_base + nt * 8 + g;
            uint32_t b0 = *reinterpret_cast<const uint32_t*>(wA + (ks * 8 + tg) * WLDH + cn * 2);
            uint32_t b1 = *reinterpret_cast<const uint32_t*>(wA + (ks * 8 + 4 + tg) * WLDH + cn * 2);
            mma16(acc[0][nt], a[0], b0, b1);
            mma16(acc[1][nt], a[1], b0, b1);
        }
    }
}

// ---- k_mix fp16 GEMM over one K=64 chunk ----
__device__ __forceinline__ void gemm_h64(const __half* __restrict__ sa,
                                         const __half* __restrict__ sb,
                                         float (&acc)[2][8][4],
                                         int m_base, int n_base, int g, int tg) {
#pragma unroll
    for (int ks = 0; ks < 4; ++ks) {
        const int kp0 = ks * 8;
        uint32_t a[2][4];
#pragma unroll
        for (int mt = 0; mt < 2; ++mt) {
            int ib = m_base + mt * 16;
            a[mt][0] = *reinterpret_cast<const uint32_t*>(sa + (kp0 + tg) * WLDH + (ib + g) * 2);
            a[mt][1] = *reinterpret_cast<const uint32_t*>(sa + (kp0 + tg) * WLDH + (ib + 8 + g) * 2);
            a[mt][2] = *reinterpret_cast<const uint32_t*>(sa + (kp0 + tg + 4) * WLDH + (ib + g) * 2);
            a[mt][3] = *reinterpret_cast<const uint32_t*>(sa + (kp0 + tg + 4) * WLDH + (ib + 8 + g) * 2);
        }
#pragma unroll
        for (int nt = 0; nt < 8; ++nt) {
            int cn = n_base + nt * 8 + g;
            uint32_t b0 = *reinterpret_cast<const uint32_t*>(sb + (kp0 + tg) * WLDH + cn * 2);
            uint32_t b1 = *reinterpret_cast<const uint32_t*>(sb + (kp0 + tg + 4) * WLDH + cn * 2);
            mma16(acc[0][nt], a[0], b0, b1);
            mma16(acc[1][nt], a[1], b0, b1);
        }
    }
}

// fp16 weight load: gmem W[k][n] -> smem [kp][n][2] halves
template <int NTHR>
__device__ __forceinline__ void loadW_h(__half* __restrict__ sw, const float* __restrict__ W, int tid) {
    for (int idx = tid; idx < 2048; idx += NTHR) {
        int kp = idx >> 5, nq = idx & 31;
        float4 v0 = __ldg(reinterpret_cast<const float4*>(W + (kp * 2) * 128) + nq);
        float4 v1 = __ldg(reinterpret_cast<const float4*>(W + (kp * 2 + 1) * 128) + nq);
        uint4 o;
        o.x = h2u(__floats2half2_rn(v0.x, v1.x));
        o.y = h2u(__floats2half2_rn(v0.y, v1.y));
        o.z = h2u(__floats2half2_rn(v0.z, v1.z));
        o.w = h2u(__floats2half2_rn(v0.w, v1.w));
        *reinterpret_cast<uint4*>(sw + kp * WLDH + nq * 8) = o;
    }
}

// combine + direct fp16 writeout to interleaved [d][k/2][j][2] halves
template <int NT>
__device__ __forceinline__ void combine_direct_h(__half* __restrict__ dstT, int krow, int j0,
                                                 const float (&acc1)[2][NT][4], const float (&acc2)[2][NT][4],
                                                 const float* __restrict__ blin, const float* __restrict__ bgat,
                                                 int m_base, int n_base, int g, int tg) {
    const size_t rowoff = (size_t)(krow >> 1) * 512 + (size_t)(krow & 1);
#pragma unroll
    for (int mt = 0; mt < 2; ++mt) {
        int j = j0 + m_base + mt * 16 + g;
#pragma unroll
        for (int nt = 0; nt < NT; ++nt) {
            int d0 = n_base + nt * 8 + tg * 2;
            float bl0 = blin[d0], bl1 = blin[d0 + 1];
            float bg0 = bgat[d0], bg1 = bgat[d0 + 1];
            __half v00 = __float2half_rn((acc1[mt][nt][0] + bl0) * sigm(acc2[mt][nt][0] + bg0));
            __half v01 = __float2half_rn((acc1[mt][nt][1] + bl1) * sigm(acc2[mt][nt][1] + bg1));
            __half v10 = __float2half_rn((acc1[mt][nt][2] + bl0) * sigm(acc2[mt][nt][2] + bg0));
            __half v11 = __float2half_rn((acc1[mt][nt][3] + bl1) * sigm(acc2[mt][nt][3] + bg1));
            __half* p0 = dstT + (((size_t)d0) << 16) + rowoff + (size_t)j * 2;
            __half* p1 = dstT + (((size_t)(d0 + 1)) << 16) + rowoff + (size_t)j * 2;
            p0[0]  = v00;  p1[0]  = v01;
            p0[16] = v10;  p1[16] = v11;
        }
    }
}

// ----- Kernel 1: LN + 5 projections, full fp16 MMA (1024 thr, 32 warps, tile 32x16) -----
__global__ void __launch_bounds__(1024, 1) k_pre(
    const float* __restrict__ x, const float* __restrict__ ng, const float* __restrict__ nb,
    const float* __restrict__ wL, const float* __restrict__ bL,
    const float* __restrict__ wR, const float* __restrict__ bR,
    const float* __restrict__ wLG, const float* __restrict__ bLG,
    const float* __restrict__ wRG, const float* __restrict__ bRG,
    const float* __restrict__ wOG, const float* __restrict__ bOG) {
    extern __shared__ __half smemh[];
    __half* sx = smemh;                      // 128 x LDAH halves
    __half* w0 = smemh + 128 * LDAH;         // 64 x WLDH halves
    __half* w1 = w0 + 64 * WLDH;

    const int tid = threadIdx.x, lane = tid & 31, warp = tid >> 5;
    const int g = lane >> 2, tg = lane & 3;
    const int r0 = blockIdx.x << 7;
    const int b = r0 >> 16, krow = (r0 >> 8) & 255, j0 = r0 & 255;
    const int m_base = (warp >> 3) * 32, n_base = (warp & 7) * 16;
    const size_t plane = ((size_t)b * 128) << 16;   // halves

    loadW_h<1024>(w0, wL, tid);
    loadW_h<1024>(w1, wLG, tid);
    {
        float4 g4 = reinterpret_cast<const float4*>(ng)[lane];
        float4 b4 = reinterpret_cast<const float4*>(nb)[lane];
        for (int row = warp * 4; row < warp * 4 + 4; ++row) {
            float4 v = reinterpret_cast<const float4*>(x + ((size_t)(r0 + row)) * 128)[lane];
            float s = v.x + v.y + v.z + v.w;
            float q = fmaf(v.x, v.x, fmaf(v.y, v.y, fmaf(v.z, v.z, v.w * v.w)));
#pragma unroll
            for (int o = 16; o; o >>= 1) {
                s += __shfl_xor_sync(0xffffffffu, s, o);
                q += __shfl_xor_sync(0xffffffffu, q, o);
            }
            float mu = s * 0.0078125f;
            float rs = rsqrtf(fmaf(-mu, mu, q * 0.0078125f) + 1e-5f);
            __half2 h0 = __floats2half2_rn(fmaf((v.x - mu) * rs, g4.x, b4.x),
                                           fmaf((v.y - mu) * rs, g4.y, b4.y));
            __half2 h1 = __floats2half2_rn(fmaf((v.z - mu) * rs, g4.z, b4.z),
                                           fmaf((v.w - mu) * rs, g4.w, b4.w));
            uint2 o2 = {h2u(h0), h2u(h1)};
            *reinterpret_cast<uint2*>(sx + row * LDAH + lane * 4) = o2;
        }
    }
    __syncthreads();

    float acc1[2][2][4], acc2[2][2][4];

    zacc2(acc1); zacc2(acc2);
    gemm_dual_h<2>(sx, w0, w1, acc1, acc2, m_base, n_base, g, tg);
    combine_direct_h<2>(reinterpret_cast<__half*>(g_leftT) + plane, krow, j0,
                        acc1, acc2, bL, bLG, m_base, n_base, g, tg);
    __syncthreads();

    loadW_h<1024>(w0, wR, tid);
    loadW_h<1024>(w1, wRG, tid);
    __syncthreads();

    zacc2(acc1); zacc2(acc2);
    gemm_dual_h<2>(sx, w0, w1, acc1, acc2, m_base, n_base, g, tg);
    combine_direct_h<2>(reinterpret_cast<__half*>(g_rightT) + plane, krow, j0,
                        acc1, acc2, bR, bRG, m_base, n_base, g, tg);
    __syncthreads();

    loadW_h<1024>(w0, wOG, tid);
    __syncthreads();

    // ogate gemm + fp16 row-major epilogue
    zacc2(acc2);
    gemm_single_h<2>(sx, w0, acc2, m_base, n_base, g, tg);
    __half* og = reinterpret_cast<__half*>(g_ogate);
#pragma unroll
    for (int mt = 0; mt < 2; ++mt) {
        int row = m_base + mt * 16 + g;
#pragma unroll
        for (int nt = 0; nt < 2; ++nt) {
            int cn = n_base + nt * 8 + tg * 2;
            float bg0 = bOG[cn], bg1 = bOG[cn + 1];
            uint32_t p0 = h2u(__floats2half2_rn(sigm(acc2[mt][nt][0] + bg0), sigm(acc2[mt][nt][1] + bg1)));
            uint32_t p1 = h2u(__floats2half2_rn(sigm(acc2[mt][nt][2] + bg0), sigm(acc2[mt][nt][3] + bg1)));
            *reinterpret_cast<uint32_t*>(og + ((size_t)(r0 + row)) * 128 + cn) = p0;
            *reinterpret_cast<uint32_t*>(og + ((size_t)(r0 + row + 8)) * 128 + cn) = p1;
        }
    }
}

// -------------------- Kernel 2: fp16 triangle einsum (2-stage, K-chunk 64) ---------------
__device__ __forceinline__ void cp_tile_h(__half* __restrict__ sdst, const __half* __restrict__ gsrc, int tid) {
#pragma unroll
    for (int m = 0; m < 4; ++m) {
        int i = tid + m * 256;
        int row = i >> 5, seg = (i & 31) * 8;
        uint32_t dst = (uint32_t)__cvta_generic_to_shared(sdst + row * WLDH + seg);
        asm volatile("cp.async.ca.shared.global [%0], [%1], 16;\n"
                     :: "r"(dst), "l"(gsrc + row * 512 + seg));
    }
}
#define CP_COMMIT asm volatile("cp.async.commit_group;\n")

__global__ void __launch_bounds__(256, 2) k_mix() {
    extern __shared__ __half smemh[];
    __half* sA[2] = {smemh, smemh + 32 * WLDH};
    __half* sB[2] = {smemh + 2 * 32 * WLDH, smemh + 3 * 32 * WLDH};

    const int tid = threadIdx.x, lane = tid & 31, warp = tid >> 5;
    const int g = lane >> 2, tg = lane & 3;
    const int b = blockIdx.z, d = blockIdx.y;
    const int i0 = (blockIdx.x >> 1) << 7, jj0 = (blockIdx.x & 1) << 7;
    const int m_base = (warp >> 1) * 32, n_base = (warp & 1) * 64;

    const size_t plane = ((size_t)(b * 128 + d)) << 16;
    const __half* __restrict__ Rp = reinterpret_cast<const __half*>(g_rightT) + plane + i0 * 2;
    const __half* __restrict__ Lp = reinterpret_cast<const __half*>(g_leftT) + plane + jj0 * 2;
    __half* __restrict__ Mp = reinterpret_cast<__half*>(g_mixT) + plane;

    float acc[2][8][4];
    zacc2(acc);

    cp_tile_h(sA[0], Rp, tid);
    cp_tile_h(sB[0], Lp, tid);
    CP_COMMIT;

#pragma unroll 1
    for (int k = 0; k < 4; ++k) {
        if (k < 3) {
            cp_tile_h(sA[(k + 1) & 1], Rp + (size_t)(k + 1) * 16384, tid);
            cp_tile_h(sB[(k + 1) & 1], Lp + (size_t)(k + 1) * 16384, tid);
            CP_COMMIT;
            asm volatile("cp.async.wait_group 1;\n");
        } else {
            asm volatile("cp.async.wait_group 0;\n");
        }
        __syncthreads();
        gemm_h64(sA[k & 1], sB[k & 1], acc, m_base, n_base, g, tg);
        __syncthreads();
    }

#pragma unroll
    for (int mt = 0; mt < 2; ++mt) {
        int row = m_base + mt * 16 + g;
#pragma unroll
        for (int nt = 0; nt < 8; ++nt) {
            int cn = n_base + nt * 8 + tg * 2;
            uint32_t p0 = h2u(__floats2half2_rn(acc[mt][nt][0], acc[mt][nt][1]));
            uint32_t p1 = h2u(__floats2half2_rn(acc[mt][nt][2], acc[mt][nt][3]));
            *reinterpret_cast<uint32_t*>(Mp + (i0 + row) * 256 + jj0 + cn) = p0;
            *reinterpret_cast<uint32_t*>(Mp + (i0 + row + 8) * 256 + jj0 + cn) = p1;
        }
    }
}

// ------- Kernel 3: LN(mixed fp16) * ogate @ w_out + b_out (64-row tiles, fp16 MMA) -------
__global__ void __launch_bounds__(256, 3) k_post(
    const float* __restrict__ ong, const float* __restrict__ onb,
    const float* __restrict__ wO, const float* __restrict__ bO,
    float* __restrict__ out) {
    extern __shared__ __half smemh[];
    __half* sx = smemh;                 // 64 x LDAH halves
    __half* sw = smemh + 64 * LDAH;     // 64 x WLDH halves

    const int tid = threadIdx.x, lane = tid & 31, warp = tid >> 5;
    const int g = lane >> 2, tg = lane & 3;
    const int r0 = blockIdx.x << 6;
    const int b = r0 >> 16, irow = (r0 >> 8) & 255, j0 = r0 & 255;
    const int m_base = (warp >> 2) * 32, n_base = (warp & 3) * 32;

    loadW_h<256>(sw, wO, tid);

    // gather mixed fp16 tile [j][d] (8 halves along j per load)
    const __half* Mh = reinterpret_cast<const __half*>(g_mixT);
    for (int i = tid; i < 1024; i += 256) {
        int d = i >> 3, sj = i & 7;
        uint4 v = *reinterpret_cast<const uint4*>(
            Mh + (((size_t)(b * 128 + d)) << 16) + irow * 256 + j0 + sj * 8);
        const __half* hv = reinterpret_cast<const __half*>(&v);
#pragma unroll
        for (int u = 0; u < 8; ++u)
            sx[(sj * 8 + u) * LDAH + d] = hv[u];
    }
    __syncthreads();

    float og_[4], ob_[4];
#pragma unroll
    for (int q_ = 0; q_ < 4; q_++) {
        og_[q_] = ong[lane + 32 * q_];
        ob_[q_] = onb[lane + 32 * q_];
    }
    const __half* gh = reinterpret_cast<const __half*>(g_ogate);
    for (int row = warp * 8; row < warp * 8 + 8; ++row) {
        float v[4];
#pragma unroll
        for (int q_ = 0; q_ < 4; q_++) v[q_] = __half2float(sx[row * LDAH + lane + 32 * q_]);
        float s = v[0] + v[1] + v[2] + v[3];
        float q = fmaf(v[0], v[0], fmaf(v[1], v[1], fmaf(v[2], v[2], v[3] * v[3])));
#pragma unroll
        for (int o = 16; o; o >>= 1) {
            s += __shfl_xor_sync(0xffffffffu, s, o);
            q += __shfl_xor_sync(0xffffffffu, q, o);
        }
        float mu = s * 0.0078125f;
        float rs = rsqrtf(fmaf(-mu, mu, q * 0.0078125f) + 1e-5f);
        const __half* gate = gh + ((size_t)(r0 + row)) * 128;
#pragma unroll
        for (int q_ = 0; q_ < 4; q_++) {
            float y = fmaf((v[q_] - mu) * rs, og_[q_], ob_[q_]) * __half2float(gate[lane + 32 * q_]);
            sx[row * LDAH + lane + 32 * q_] = __float2half_rn(y);
        }
    }
    __syncthreads();

    float acc[2][4][4];
    zacc2(acc);
    gemm_single_h<4>(sx, sw, acc, m_base, n_base, g, tg);

#pragma unroll
    for (int mt = 0; mt < 2; ++mt) {
        int row = m_base + mt * 16 + g;
#pragma unroll
        for (int nt = 0; nt < 4; ++nt) {
            int cn = n_base + nt * 8 + tg * 2;
            float b0v = bO[cn], b1v = bO[cn + 1];
            float2 p0 = {acc[mt][nt][0] + b0v, acc[mt][nt][1] + b1v};
            float2 p1 = {acc[mt][nt][2] + b0v, acc[mt][nt][3] + b1v};
            *reinterpret_cast<float2*>(out + ((size_t)(r0 + row)) * 128 + cn) = p0;
            *reinterpret_cast<float2*>(out + ((size_t)(r0 + row + 8)) * 128 + cn) = p1;
        }
    }
}

extern "C" void kernel_launch(void* const* d_in, const int* in_sizes, int n_in,
                              void* d_out, int out_size) {
    const float* x    = (const float*)d_in[0];
    const float* ng   = (const float*)d_in[1];
    const float* nb   = (const float*)d_in[2];
    const float* wL   = (const float*)d_in[3];
    const float* bL   = (const float*)d_in[4];
    const float* wR   = (const float*)d_in[5];
    const float* bR   = (const float*)d_in[6];
    const float* wLG  = (const float*)d_in[7];
    const float* bLG  = (const float*)d_in[8];
    const float* wRG  = (const float*)d_in[9];
    const float* bRG  = (const float*)d_in[10];
    const float* wOG  = (const float*)d_in[11];
    const float* bOG  = (const float*)d_in[12];
    const float* ong  = (const float*)d_in[13];
    const float* onb  = (const float*)d_in[14];
    const float* wO   = (const float*)d_in[15];
    const float* bO   = (const float*)d_in[16];
    float* out = (float*)d_out;

    cudaFuncSetAttribute(k_pre,  cudaFuncAttributeMaxDynamicSharedMemorySize, SMEM_PRE);
    cudaFuncSetAttribute(k_mix,  cudaFuncAttributeMaxDynamicSharedMemorySize, SMEM_MIX);
    cudaFuncSetAttribute(k_post, cudaFuncAttributeMaxDynamicSharedMemorySize, SMEM_POST);

    k_pre<<<2048, 1024, SMEM_PRE>>>(x, ng, nb, wL, bL, wR, bR, wLG, bLG, wRG, bRG, wOG, bOG);
    k_mix<<<dim3(4, 128, 4), 256, SMEM_MIX>>>();
    k_post<<<4096, 256, SMEM_POST>>>(ong, onb, wO, bO, out);
}

// round 15
// speedup vs baseline: 1.7095x; 1.0269x over previous
#include <cuda_runtime.h>
#include <cuda_fp16.h>
#include <cstdint>

// x [4,256,256,128], DIM=HID=128, R = 262144 rows.
constexpr int LDAH = 136;  // fp16 activation ld in halves (272B; %128==16 -> CF)
constexpr int WLDH = 272;  // fp16 k-pair tiles: halves per kp-row (544B; %128==32 -> CF)

constexpr int SMEM_PRE  = (128 * LDAH + 4 * 64 * WLDH) * 2;  // 174,080
constexpr int SMEM_MIX  = 4 * 32 * WLDH * 2;                 // 69,632
constexpr int SMEM_POST = (64 * LDAH + 64 * WLDH) * 2;       // 52,224

// Scratch (device globals). All intermediates fp16 halves.
__device__ float g_leftT [33554432];  // halves: [b][d][k/2][j][2]
__device__ float g_rightT[33554432];  // halves: [b][d][k/2][i][2]
__device__ float g_ogate [16777216];  // halves: [r][d]
__device__ float g_mixT  [16777216];  // halves: [b][d][i][j]

__device__ __forceinline__ uint32_t h2u(__half2 h) {
    return *reinterpret_cast<uint32_t*>(&h);
}
__device__ __forceinline__ float sigm(float x) { return 1.0f / (1.0f + __expf(-x)); }

__device__ __forceinline__ void mma16(float c[4], const uint32_t a[4], uint32_t b0, uint32_t b1) {
    asm volatile(
        "mma.sync.aligned.m16n8k16.row.col.f32.f16.f16.f32 "
        "{%0,%1,%2,%3},{%4,%5,%6,%7},{%8,%9},{%0,%1,%2,%3};\n"
        : "+f"(c[0]), "+f"(c[1]), "+f"(c[2]), "+f"(c[3])
        : "r"(a[0]), "r"(a[1]), "r"(a[2]), "r"(a[3]), "r"(b0), "r"(b1));
}

template <int NT>
__device__ __forceinline__ void zacc2(float (&a)[2][NT][4]) {
#pragma unroll
    for (int i = 0; i < 2; i++)
#pragma unroll
        for (int j = 0; j < NT; j++)
#pragma unroll
            for (int k = 0; k < 4; k++) a[i][j][k] = 0.f;
}

// ---- fp16 dual GEMM: A row-major fp16 (ld=LDAH halves), B [kp][n][2] ----
template <int NT>
__device__ __forceinline__ void gemm_dual_h(const __half* __restrict__ sa,
                                            const __half* __restrict__ wA,
                                            const __half* __restrict__ wB,
                                            float (&acc1)[2][NT][4], float (&acc2)[2][NT][4],
                                            int m_base, int n_base, int g, int tg) {
#pragma unroll
    for (int ks = 0; ks < 8; ++ks) {       // K=16 per step
        uint32_t a[2][4];
#pragma unroll
        for (int mt = 0; mt < 2; ++mt) {
            int r = m_base + mt * 16;
            const __half* p0 = sa + (r + g) * LDAH + ks * 16 + tg * 2;
            const __half* p1 = sa + (r + 8 + g) * LDAH + ks * 16 + tg * 2;
            a[mt][0] = *reinterpret_cast<const uint32_t*>(p0);
            a[mt][1] = *reinterpret_cast<const uint32_t*>(p1);
            a[mt][2] = *reinterpret_cast<const uint32_t*>(p0 + 8);
            a[mt][3] = *reinterpret_cast<const uint32_t*>(p1 + 8);
        }
#pragma unroll
        for (int nt = 0; nt < NT; ++nt) {
            int cn = n_base + nt * 8 + g;
            uint32_t b00 = *reinterpret_cast<const uint32_t*>(wA + (ks * 8 + tg) * WLDH + cn * 2);
            uint32_t b01 = *reinterpret_cast<const uint32_t*>(wA + (ks * 8 + 4 + tg) * WLDH + cn * 2);
            uint32_t b10 = *reinterpret_cast<const uint32_t*>(wB + (ks * 8 + tg) * WLDH + cn * 2);
            uint32_t b11 = *reinterpret_cast<const uint32_t*>(wB + (ks * 8 + 4 + tg) * WLDH + cn * 2);
            mma16(acc1[0][nt], a[0], b00, b01);
            mma16(acc1[1][nt], a[1], b00, b01);
            mma16(acc2[0][nt], a[0], b10, b11);
            mma16(acc2[1][nt], a[1], b10, b11);
        }
    }
}

template <int NT>
__device__ __forceinline__ void gemm_single_h(const __half* __restrict__ sa,
                                              const __half* __restrict__ wA,
                                              float (&acc)[2][NT][4],
                                              int m_base, int n_base, int g, int tg) {
#pragma unroll
    for (int ks = 0; ks < 8; ++ks) {
        uint32_t a[2][4];
#pragma unroll
        for (int mt = 0; mt < 2; ++mt) {
            int r = m_base + mt * 16;
            const __half* p0 = sa + (r + g) * LDAH + ks * 16 + tg * 2;
            const __half* p1 = sa + (r + 8 + g) * LDAH + ks * 16 + tg * 2;
            a[mt][0] = *reinterpret_cast<const uint32_t*>(p0);
            a[mt][1] = *reinterpret_cast<const uint32_t*>(p1);
            a[mt][2] = *reinterpret_cast<const uint32_t*>(p0 + 8);
            a[mt][3] = *reinterpret_cast<const uint32_t*>(p1 + 8);
        }
#pragma unroll
        for (int nt = 0; nt < NT; ++nt) {
            int cn = n_base + nt * 8 + g;
            uint32_t b0 = *reinterpret_cast<const uint32_t*>(wA + (ks * 8 + tg) * WLDH + cn * 2);
            uint32_t b1 = *reinterpret_cast<const uint32_t*>(wA + (ks * 8 + 4 + tg) * WLDH + cn * 2);
            mma16(acc[0][nt], a[0], b0, b1);
            mma16(acc[1][nt], a[1], b0, b1);
        }
    }
}

// ---- k_mix fp16 GEMM over one K=64 chunk ----
__device__ __forceinline__ void gemm_h64(const __half* __restrict__ sa,
                                         const __half* __restrict__ sb,
                                         float (&acc)[2][8][4],
                                         int m_base, int n_base, int g, int tg) {
#pragma unroll
    for (int ks = 0; ks < 4; ++ks) {
        const int kp0 = ks * 8;
        uint32_t a[2][4];
#pragma unroll
        for (int mt = 0; mt < 2; ++mt) {
            int ib = m_base + mt * 16;
            a[mt][0] = *reinterpret_cast<const uint32_t*>(sa + (kp0 + tg) * WLDH + (ib + g) * 2);
            a[mt][1] = *reinterpret_cast<const uint32_t*>(sa + (kp0 + tg) * WLDH + (ib + 8 + g) * 2);
            a[mt][2] = *reinterpret_cast<const uint32_t*>(sa + (kp0 + tg + 4) * WLDH + (ib + g) * 2);
            a[mt][3] = *reinterpret_cast<const uint32_t*>(sa + (kp0 + tg + 4) * WLDH + (ib + 8 + g) * 2);
        }
#pragma unroll
        for (int nt = 0; nt < 8; ++nt) {
            int cn = n_base + nt * 8 + g;
            uint32_t b0 = *reinterpret_cast<const uint32_t*>(sb + (kp0 + tg) * WLDH + cn * 2);
            uint32_t b1 = *reinterpret_cast<const uint32_t*>(sb + (kp0 + tg + 4) * WLDH + cn * 2);
            mma16(acc[0][nt], a[0], b0, b1);
            mma16(acc[1][nt], a[1], b0, b1);
        }
    }
}

// fp16 weight load: gmem W[k][n] -> smem [kp][n][2] halves
template <int NTHR>
__device__ __forceinline__ void loadW_h(__half* __restrict__ sw, const float* __restrict__ W, int tid) {
    for (int idx = tid; idx < 2048; idx += NTHR) {
        int kp = idx >> 5, nq = idx & 31;
        float4 v0 = __ldg(reinterpret_cast<const float4*>(W + (kp * 2) * 128) + nq);
        float4 v1 = __ldg(reinterpret_cast<const float4*>(W + (kp * 2 + 1) * 128) + nq);
        uint4 o;
        o.x = h2u(__floats2half2_rn(v0.x, v1.x));
        o.y = h2u(__floats2half2_rn(v0.y, v1.y));
        o.z = h2u(__floats2half2_rn(v0.z, v1.z));
        o.w = h2u(__floats2half2_rn(v0.w, v1.w));
        *reinterpret_cast<uint4*>(sw + kp * WLDH + nq * 8) = o;
    }
}

// combine + direct fp16 writeout to interleaved [d][k/2][j][2] halves
template <int NT>
__device__ __forceinline__ void combine_direct_h(__half* __restrict__ dstT, int krow, int j0,
                                                 const float (&acc1)[2][NT][4], const float (&acc2)[2][NT][4],
                                                 const float* __restrict__ blin, const float* __restrict__ bgat,
                                                 int m_base, int n_base, int g, int tg) {
    const size_t rowoff = (size_t)(krow >> 1) * 512 + (size_t)(krow & 1);
#pragma unroll
    for (int mt = 0; mt < 2; ++mt) {
        int j = j0 + m_base + mt * 16 + g;
#pragma unroll
        for (int nt = 0; nt < NT; ++nt) {
            int d0 = n_base + nt * 8 + tg * 2;
            float bl0 = blin[d0], bl1 = blin[d0 + 1];
            float bg0 = bgat[d0], bg1 = bgat[d0 + 1];
            __half v00 = __float2half_rn((acc1[mt][nt][0] + bl0) * sigm(acc2[mt][nt][0] + bg0));
            __half v01 = __float2half_rn((acc1[mt][nt][1] + bl1) * sigm(acc2[mt][nt][1] + bg1));
            __half v10 = __float2half_rn((acc1[mt][nt][2] + bl0) * sigm(acc2[mt][nt][2] + bg0));
            __half v11 = __float2half_rn((acc1[mt][nt][3] + bl1) * sigm(acc2[mt][nt][3] + bg1));
            __half* p0 = dstT + (((size_t)d0) << 16) + rowoff + (size_t)j * 2;
            __half* p1 = dstT + (((size_t)(d0 + 1)) << 16) + rowoff + (size_t)j * 2;
            p0[0]  = v00;  p1[0]  = v01;
            p0[16] = v10;  p1[16] = v11;
        }
    }
}

// -- Kernel 1: LN + 5 projections, 4-buffer preload (1024 thr, tile 32x16, 3 syncs) --
__global__ void __launch_bounds__(1024, 1) k_pre(
    const float* __restrict__ x, const float* __restrict__ ng, const float* __restrict__ nb,
    const float* __restrict__ wL, const float* __restrict__ bL,
    const float* __restrict__ wR, const float* __restrict__ bR,
    const float* __restrict__ wLG, const float* __restrict__ bLG,
    const float* __restrict__ wRG, const float* __restrict__ bRG,
    const float* __restrict__ wOG, const float* __restrict__ bOG) {
    extern __shared__ __half smemh[];
    __half* sx = smemh;                      // 128 x LDAH halves
    __half* w0 = smemh + 128 * LDAH;         // 4 x (64 x WLDH halves)
    __half* w1 = w0 + 64 * WLDH;
    __half* w2 = w1 + 64 * WLDH;
    __half* w3 = w2 + 64 * WLDH;

    const int tid = threadIdx.x, lane = tid & 31, warp = tid >> 5;
    const int g = lane >> 2, tg = lane & 3;
    const int r0 = blockIdx.x << 7;
    const int b = r0 >> 16, krow = (r0 >> 8) & 255, j0 = r0 & 255;
    const int m_base = (warp >> 3) * 32, n_base = (warp & 7) * 16;
    const size_t plane = ((size_t)b * 128) << 16;   // halves

    // Phase A: preload ALL pair weights + LN
    loadW_h<1024>(w0, wL, tid);
    loadW_h<1024>(w1, wLG, tid);
    loadW_h<1024>(w2, wR, tid);
    loadW_h<1024>(w3, wRG, tid);
    {
        float4 g4 = reinterpret_cast<const float4*>(ng)[lane];
        float4 b4 = reinterpret_cast<const float4*>(nb)[lane];
        for (int row = warp * 4; row < warp * 4 + 4; ++row) {
            float4 v = reinterpret_cast<const float4*>(x + ((size_t)(r0 + row)) * 128)[lane];
            float s = v.x + v.y + v.z + v.w;
            float q = fmaf(v.x, v.x, fmaf(v.y, v.y, fmaf(v.z, v.z, v.w * v.w)));
#pragma unroll
            for (int o = 16; o; o >>= 1) {
                s += __shfl_xor_sync(0xffffffffu, s, o);
                q += __shfl_xor_sync(0xffffffffu, q, o);
            }
            float mu = s * 0.0078125f;
            float rs = rsqrtf(fmaf(-mu, mu, q * 0.0078125f) + 1e-5f);
            __half2 h0 = __floats2half2_rn(fmaf((v.x - mu) * rs, g4.x, b4.x),
                                           fmaf((v.y - mu) * rs, g4.y, b4.y));
            __half2 h1 = __floats2half2_rn(fmaf((v.z - mu) * rs, g4.z, b4.z),
                                           fmaf((v.w - mu) * rs, g4.w, b4.w));
            uint2 o2 = {h2u(h0), h2u(h1)};
            *reinterpret_cast<uint2*>(sx + row * LDAH + lane * 4) = o2;
        }
    }
    __syncthreads();

    float acc1[2][2][4], acc2[2][2][4];

    // Phase B: left pair + writeout
    zacc2(acc1); zacc2(acc2);
    gemm_dual_h<2>(sx, w0, w1, acc1, acc2, m_base, n_base, g, tg);
    combine_direct_h<2>(reinterpret_cast<__half*>(g_leftT) + plane, krow, j0,
                        acc1, acc2, bL, bLG, m_base, n_base, g, tg);
    __syncthreads();

    // Phase C: right pair + writeout; wOG load hidden under the gemm (w0 is dead)
    loadW_h<1024>(w0, wOG, tid);
    zacc2(acc1); zacc2(acc2);
    gemm_dual_h<2>(sx, w2, w3, acc1, acc2, m_base, n_base, g, tg);
    combine_direct_h<2>(reinterpret_cast<__half*>(g_rightT) + plane, krow, j0,
                        acc1, acc2, bR, bRG, m_base, n_base, g, tg);
    __syncthreads();

    // Phase D: ogate gemm + fp16 row-major epilogue
    zacc2(acc2);
    gemm_single_h<2>(sx, w0, acc2, m_base, n_base, g, tg);
    __half* og = reinterpret_cast<__half*>(g_ogate);
#pragma unroll
    for (int mt = 0; mt < 2; ++mt) {
        int row = m_base + mt * 16 + g;
#pragma unroll
        for (int nt = 0; nt < 2; ++nt) {
            int cn = n_base + nt * 8 + tg * 2;
            float bg0 = bOG[cn], bg1 = bOG[cn + 1];
            uint32_t p0 = h2u(__floats2half2_rn(sigm(acc2[mt][nt][0] + bg0), sigm(acc2[mt][nt][1] + bg1)));
            uint32_t p1 = h2u(__floats2half2_rn(sigm(acc2[mt][nt][2] + bg0), sigm(acc2[mt][nt][3] + bg1)));
            *reinterpret_cast<uint32_t*>(og + ((size_t)(r0 + row)) * 128 + cn) = p0;
            *reinterpret_cast<uint32_t*>(og + ((size_t)(r0 + row + 8)) * 128 + cn) = p1;
        }
    }
}

// -------------------- Kernel 2: fp16 triangle einsum (2-stage, K-chunk 64) ---------------
__device__ __forceinline__ void cp_tile_h(__half* __restrict__ sdst, const __half* __restrict__ gsrc, int tid) {
#pragma unroll
    for (int m = 0; m < 4; ++m) {
        int i = tid + m * 256;
        int row = i >> 5, seg = (i & 31) * 8;
        uint32_t dst = (uint32_t)__cvta_generic_to_shared(sdst + row * WLDH + seg);
        asm volatile("cp.async.ca.shared.global [%0], [%1], 16;\n"
                     :: "r"(dst), "l"(gsrc + row * 512 + seg));
    }
}
#define CP_COMMIT asm volatile("cp.async.commit_group;\n")

__global__ void __launch_bounds__(256, 2) k_mix() {
    extern __shared__ __half smemh[];
    __half* sA[2] = {smemh, smemh + 32 * WLDH};
    __half* sB[2] = {smemh + 2 * 32 * WLDH, smemh + 3 * 32 * WLDH};

    const int tid = threadIdx.x, lane = tid & 31, warp = tid >> 5;
    const int g = lane >> 2, tg = lane & 3;
    const int b = blockIdx.z, d = blockIdx.y;
    const int i0 = (blockIdx.x >> 1) << 7, jj0 = (blockIdx.x & 1) << 7;
    const int m_base = (warp >> 1) * 32, n_base = (warp & 1) * 64;

    const size_t plane = ((size_t)(b * 128 + d)) << 16;
    const __half* __restrict__ Rp = reinterpret_cast<const __half*>(g_rightT) + plane + i0 * 2;
    const __half* __restrict__ Lp = reinterpret_cast<const __half*>(g_leftT) + plane + jj0 * 2;
    __half* __restrict__ Mp = reinterpret_cast<__half*>(g_mixT) + plane;

    float acc[2][8][4];
    zacc2(acc);

    cp_tile_h(sA[0], Rp, tid);
    cp_tile_h(sB[0], Lp, tid);
    CP_COMMIT;

#pragma unroll 1
    for (int k = 0; k < 4; ++k) {
        if (k < 3) {
            cp_tile_h(sA[(k + 1) & 1], Rp + (size_t)(k + 1) * 16384, tid);
            cp_tile_h(sB[(k + 1) & 1], Lp + (size_t)(k + 1) * 16384, tid);
            CP_COMMIT;
            asm volatile("cp.async.wait_group 1;\n");
        } else {
            asm volatile("cp.async.wait_group 0;\n");
        }
        __syncthreads();
        gemm_h64(sA[k & 1], sB[k & 1], acc, m_base, n_base, g, tg);
        __syncthreads();
    }

#pragma unroll
    for (int mt = 0; mt < 2; ++mt) {
        int row = m_base + mt * 16 + g;
#pragma unroll
        for (int nt = 0; nt < 8; ++nt) {
            int cn = n_base + nt * 8 + tg * 2;
            uint32_t p0 = h2u(__floats2half2_rn(acc[mt][nt][0], acc[mt][nt][1]));
            uint32_t p1 = h2u(__floats2half2_rn(acc[mt][nt][2], acc[mt][nt][3]));
            *reinterpret_cast<uint32_t*>(Mp + (i0 + row) * 256 + jj0 + cn) = p0;
            *reinterpret_cast<uint32_t*>(Mp + (i0 + row + 8) * 256 + jj0 + cn) = p1;
        }
    }
}

// ------- Kernel 3: LN(mixed fp16) * ogate @ w_out + b_out (64-row tiles, fp16 MMA) -------
__global__ void __launch_bounds__(256, 3) k_post(
    const float* __restrict__ ong, const float* __restrict__ onb,
    const float* __restrict__ wO, const float* __restrict__ bO,
    float* __restrict__ out) {
    extern __shared__ __half smemh[];
    __half* sx = smemh;                 // 64 x LDAH halves
    __half* sw = smemh + 64 * LDAH;     // 64 x WLDH halves

    const int tid = threadIdx.x, lane = tid & 31, warp = tid >> 5;
    const int g = lane >> 2, tg = lane & 3;
    const int r0 = blockIdx.x << 6;
    const int b = r0 >> 16, irow = (r0 >> 8) & 255, j0 = r0 & 255;
    const int m_base = (warp >> 2) * 32, n_base = (warp & 3) * 32;

    loadW_h<256>(sw, wO, tid);

    const __half* Mh = reinterpret_cast<const __half*>(g_mixT);
    for (int i = tid; i < 1024; i += 256) {
        int d = i >> 3, sj = i & 7;
        uint4 v = *reinterpret_cast<const uint4*>(
            Mh + (((size_t)(b * 128 + d)) << 16) + irow * 256 + j0 + sj * 8);
        const __half* hv = reinterpret_cast<const __half*>(&v);
#pragma unroll
        for (int u = 0; u < 8; ++u)
            sx[(sj * 8 + u) * LDAH + d] = hv[u];
    }
    __syncthreads();

    float og_[4], ob_[4];
#pragma unroll
    for (int q_ = 0; q_ < 4; q_++) {
        og_[q_] = ong[lane + 32 * q_];
        ob_[q_] = onb[lane + 32 * q_];
    }
    const __half* gh = reinterpret_cast<const __half*>(g_ogate);
    for (int row = warp * 8; row < warp * 8 + 8; ++row) {
        float v[4];
#pragma unroll
        for (int q_ = 0; q_ < 4; q_++) v[q_] = __half2float(sx[row * LDAH + lane + 32 * q_]);
        float s = v[0] + v[1] + v[2] + v[3];
        float q = fmaf(v[0], v[0], fmaf(v[1], v[1], fmaf(v[2], v[2], v[3] * v[3])));
#pragma unroll
        for (int o = 16; o; o >>= 1) {
            s += __shfl_xor_sync(0xffffffffu, s, o);
            q += __shfl_xor_sync(0xffffffffu, q, o);
        }
        float mu = s * 0.0078125f;
        float rs = rsqrtf(fmaf(-mu, mu, q * 0.0078125f) + 1e-5f);
        const __half* gate = gh + ((size_t)(r0 + row)) * 128;
#pragma unroll
        for (int q_ = 0; q_ < 4; q_++) {
            float y = fmaf((v[q_] - mu) * rs, og_[q_], ob_[q_]) * __half2float(gate[lane + 32 * q_]);
            sx[row * LDAH + lane + 32 * q_] = __float2half_rn(y);
        }
    }
    __syncthreads();

    float acc[2][4][4];
    zacc2(acc);
    gemm_single_h<4>(sx, sw, acc, m_base, n_base, g, tg);

#pragma unroll
    for (int mt = 0; mt < 2; ++mt) {
        int row = m_base + mt * 16 + g;
#pragma unroll
        for (int nt = 0; nt < 4; ++nt) {
            int cn = n_base + nt * 8 + tg * 2;
            float b0v = bO[cn], b1v = bO[cn + 1];
            float2 p0 = {acc[mt][nt][0] + b0v, acc[mt][nt][1] + b1v};
            float2 p1 = {acc[mt][nt][2] + b0v, acc[mt][nt][3] + b1v};
            *reinterpret_cast<float2*>(out + ((size_t)(r0 + row)) * 128 + cn) = p0;
            *reinterpret_cast<float2*>(out + ((size_t)(r0 + row + 8)) * 128 + cn) = p1;
        }
    }
}

extern "C" void kernel_launch(void* const* d_in, const int* in_sizes, int n_in,
                              void* d_out, int out_size) {
    const float* x    = (const float*)d_in[0];
    const float* ng   = (const float*)d_in[1];
    const float* nb   = (const float*)d_in[2];
    const float* wL   = (const float*)d_in[3];
    const float* bL   = (const float*)d_in[4];
    const float* wR   = (const float*)d_in[5];
    const float* bR   = (const float*)d_in[6];
    const float* wLG  = (const float*)d_in[7];
    const float* bLG  = (const float*)d_in[8];
    const float* wRG  = (const float*)d_in[9];
    const float* bRG  = (const float*)d_in[10];
    const float* wOG  = (const float*)d_in[11];
    const float* bOG  = (const float*)d_in[12];
    const float* ong  = (const float*)d_in[13];
    const float* onb  = (const float*)d_in[14];
    const float* wO   = (const float*)d_in[15];
    const float* bO   = (const float*)d_in[16];
    float* out = (float*)d_out;

    cudaFuncSetAttribute(k_pre,  cudaFuncAttributeMaxDynamicSharedMemorySize, SMEM_PRE);
    cudaFuncSetAttribute(k_mix,  cudaFuncAttributeMaxDynamicSharedMemorySize, SMEM_MIX);
    cudaFuncSetAttribute(k_post, cudaFuncAttributeMaxDynamicSharedMemorySize, SMEM_POST);

    k_pre<<<2048, 1024, SMEM_PRE>>>(x, ng, nb, wL, bL, wR, bR, wLG, bLG, wRG, bRG, wOG, bOG);
    k_mix<<<dim3(4, 128, 4), 256, SMEM_MIX>>>();
    k_post<<<4096, 256, SMEM_POST>>>(ong, onb, wO, bO, out);
}